// round 1
// baseline (speedup 1.0000x reference)
#include <cuda_runtime.h>
#include <math.h>

#define BATCH 2
#define SEQ   4096
#define H     1024
#define E     8
#define TOPK  2
#define I     1408
#define T     (BATCH*SEQ)   // 8192 tokens

// ---------------- scratch (device globals; no runtime allocation) ----------------
__device__ float g_act [(size_t)E * T * I];   // routed silu(g)*u, per-expert fixed capacity
__device__ float g_acts[(size_t)T * I];       // shared-expert silu(g)*u
__device__ int   g_tok [E * T];               // per-expert token lists
__device__ float g_cw  [E * T];               // per-expert combine weights
__device__ int   g_cnt [E];
__device__ float g_sg  [T];                   // sigmoid shared gate
__device__ int   g_topk_i[T * TOPK];
__device__ float g_topk_w[T * TOPK];

// ---------------- router: logits -> softmax -> top2 -> renorm; + shared gate ----
__global__ __launch_bounds__(256) void router_kernel(
    const float* __restrict__ x,
    const float* __restrict__ gate_w,
    const float* __restrict__ shared_gate_w)
{
    __shared__ float sgw[9][H];   // 8 expert gates + shared gate = 36KB
    for (int idx = threadIdx.x; idx < 9 * H; idx += blockDim.x) {
        int e = idx / H, h = idx % H;
        sgw[e][h] = (e < 8) ? gate_w[idx] : shared_gate_w[h];
    }
    __syncthreads();

    int warp = threadIdx.x >> 5, lane = threadIdx.x & 31;
    int t = blockIdx.x * 8 + warp;
    const float4* xr = (const float4*)(x + (size_t)t * H);

    float acc[9];
    #pragma unroll
    for (int e = 0; e < 9; e++) acc[e] = 0.f;

    for (int c = lane; c < H / 4; c += 32) {
        float4 xv = xr[c];
        #pragma unroll
        for (int e = 0; e < 9; e++) {
            float4 gv = ((const float4*)sgw[e])[c];
            acc[e] += xv.x * gv.x + xv.y * gv.y + xv.z * gv.z + xv.w * gv.w;
        }
    }
    #pragma unroll
    for (int e = 0; e < 9; e++)
        #pragma unroll
        for (int o = 16; o > 0; o >>= 1)
            acc[e] += __shfl_xor_sync(0xffffffffu, acc[e], o);

    if (lane == 0) {
        float m = acc[0];
        #pragma unroll
        for (int e = 1; e < 8; e++) m = fmaxf(m, acc[e]);
        float p[8];
        #pragma unroll
        for (int e = 0; e < 8; e++) p[e] = __expf(acc[e] - m);
        // top-2 (first-index wins ties, matching lax.top_k)
        int i0 = 0;
        #pragma unroll
        for (int e = 1; e < 8; e++) if (p[e] > p[i0]) i0 = e;
        int i1 = -1;
        #pragma unroll
        for (int e = 0; e < 8; e++) {
            if (e == i0) continue;
            if (i1 < 0 || p[e] > p[i1]) i1 = e;
        }
        float w0 = p[i0], w1 = p[i1], ws = w0 + w1;  // softmax denom cancels in renorm
        g_topk_i[t * 2 + 0] = i0;  g_topk_w[t * 2 + 0] = w0 / ws;
        g_topk_i[t * 2 + 1] = i1;  g_topk_w[t * 2 + 1] = w1 / ws;
        g_sg[t] = 1.f / (1.f + __expf(-acc[8]));
    }
}

__global__ void zero_cnt_kernel() {
    if (threadIdx.x < E) g_cnt[threadIdx.x] = 0;
}

__global__ void scatter_kernel() {
    int t = blockIdx.x * blockDim.x + threadIdx.x;
    if (t >= T) return;
    #pragma unroll
    for (int k = 0; k < TOPK; k++) {
        int e = g_topk_i[t * 2 + k];
        float w = g_topk_w[t * 2 + k];
        int pos = atomicAdd(&g_cnt[e], 1);
        g_tok[e * T + pos] = t;
        g_cw [e * T + pos] = w;
    }
}

// -------- phase A: act = silu(x @ Wg) * (x @ Wu), gathered rows, fused --------
// Tile: 64 rows x 128 cols x 16 K. 256 threads, each 4x8 per output matrix.
__global__ __launch_bounds__(256, 1) void mlp_a_kernel(
    const float* __restrict__ x,
    const float* __restrict__ wg_base,
    const float* __restrict__ wu_base,
    int routed)
{
    int e = blockIdx.z;
    int n_rows;
    const float *wg, *wu;
    float* act;
    const int* tok = nullptr;
    if (routed) {
        n_rows = g_cnt[e];
        wg  = wg_base + (size_t)e * H * I;
        wu  = wu_base + (size_t)e * H * I;
        act = g_act + (size_t)e * T * I;
        tok = g_tok + e * T;
    } else {
        n_rows = T; wg = wg_base; wu = wu_base; act = g_acts;
    }
    int m0 = blockIdx.y * 64;
    if (m0 >= n_rows) return;
    int n0 = blockIdx.x * 128;

    __shared__ float As[16][64];
    __shared__ float Bg[16][128];
    __shared__ float Bu[16][128];
    __shared__ int srow[64];

    int tid = threadIdx.x;
    if (tid < 64) {
        int r = m0 + tid;
        srow[tid] = routed ? ((r < n_rows) ? tok[r] : 0) : r;
    }
    __syncthreads();

    int tx = tid & 15, ty = tid >> 4;
    float cg[4][8], cu[4][8];
    #pragma unroll
    for (int m = 0; m < 4; m++)
        #pragma unroll
        for (int j = 0; j < 8; j++) { cg[m][j] = 0.f; cu[m][j] = 0.f; }

    int ar = tid >> 2;              // A row 0..63
    int ak = (tid & 3) * 4;         // A k-offset 0,4,8,12
    const float* arow = x + (size_t)srow[ar] * H + ak;
    int bn = (tid & 31) * 4;        // B col 0..124
    int bk = tid >> 5;              // B k row 0..7 (and +8)

    for (int k0 = 0; k0 < H; k0 += 16) {
        float4 av = *(const float4*)(arow + k0);
        As[ak + 0][ar] = av.x; As[ak + 1][ar] = av.y;
        As[ak + 2][ar] = av.z; As[ak + 3][ar] = av.w;
        *(float4*)&Bg[bk    ][bn] = *(const float4*)(wg + (size_t)(k0 + bk    ) * I + n0 + bn);
        *(float4*)&Bu[bk    ][bn] = *(const float4*)(wu + (size_t)(k0 + bk    ) * I + n0 + bn);
        *(float4*)&Bg[bk + 8][bn] = *(const float4*)(wg + (size_t)(k0 + bk + 8) * I + n0 + bn);
        *(float4*)&Bu[bk + 8][bn] = *(const float4*)(wu + (size_t)(k0 + bk + 8) * I + n0 + bn);
        __syncthreads();
        #pragma unroll
        for (int kk = 0; kk < 16; kk++) {
            float a[4];
            #pragma unroll
            for (int m = 0; m < 4; m++) a[m] = As[kk][ty * 4 + m];
            #pragma unroll
            for (int j = 0; j < 8; j++) {
                float bg = Bg[kk][tx + 16 * j];
                float bu = Bu[kk][tx + 16 * j];
                #pragma unroll
                for (int m = 0; m < 4; m++) {
                    cg[m][j] += a[m] * bg;
                    cu[m][j] += a[m] * bu;
                }
            }
        }
        __syncthreads();
    }

    #pragma unroll
    for (int m = 0; m < 4; m++) {
        int r = m0 + ty * 4 + m;
        if (r >= n_rows) continue;
        float* orow = act + (size_t)r * I + n0;
        #pragma unroll
        for (int j = 0; j < 8; j++) {
            float g = cg[m][j], u = cu[m][j];
            orow[tx + 16 * j] = g / (1.f + __expf(-g)) * u;   // silu(g)*u
        }
    }
}

// -------- phase B: out += combine_w * (act @ Wd)  (routed: atomicAdd; shared: store) --
__global__ __launch_bounds__(256, 1) void mlp_b_kernel(
    const float* __restrict__ wd_base,
    float* __restrict__ out,
    int routed)
{
    int e = blockIdx.z;
    int n_rows;
    const float *wd, *act;
    const int* tok = nullptr;
    const float* cw = nullptr;
    if (routed) {
        n_rows = g_cnt[e];
        wd  = wd_base + (size_t)e * I * H;
        act = g_act + (size_t)e * T * I;
        tok = g_tok + e * T;
        cw  = g_cw  + e * T;
    } else {
        n_rows = T; wd = wd_base; act = g_acts;
    }
    int m0 = blockIdx.y * 64;
    if (m0 >= n_rows) return;
    int n0 = blockIdx.x * 128;

    __shared__ float As[16][64];
    __shared__ float Bs[16][128];

    int tid = threadIdx.x;
    int tx = tid & 15, ty = tid >> 4;
    float c[4][8];
    #pragma unroll
    for (int m = 0; m < 4; m++)
        #pragma unroll
        for (int j = 0; j < 8; j++) c[m][j] = 0.f;

    int ar = tid >> 2;
    int ak = (tid & 3) * 4;
    int arr = m0 + ar;
    bool avalid = arr < n_rows;
    const float* arow = act + (size_t)arr * I + ak;   // arr < T always: in-bounds
    int bn = (tid & 31) * 4;
    int bk = tid >> 5;

    for (int k0 = 0; k0 < I; k0 += 16) {
        float4 av = avalid ? *(const float4*)(arow + k0) : make_float4(0.f, 0.f, 0.f, 0.f);
        As[ak + 0][ar] = av.x; As[ak + 1][ar] = av.y;
        As[ak + 2][ar] = av.z; As[ak + 3][ar] = av.w;
        *(float4*)&Bs[bk    ][bn] = *(const float4*)(wd + (size_t)(k0 + bk    ) * H + n0 + bn);
        *(float4*)&Bs[bk + 8][bn] = *(const float4*)(wd + (size_t)(k0 + bk + 8) * H + n0 + bn);
        __syncthreads();
        #pragma unroll
        for (int kk = 0; kk < 16; kk++) {
            float a[4];
            #pragma unroll
            for (int m = 0; m < 4; m++) a[m] = As[kk][ty * 4 + m];
            #pragma unroll
            for (int j = 0; j < 8; j++) {
                float b = Bs[kk][tx + 16 * j];
                #pragma unroll
                for (int m = 0; m < 4; m++) c[m][j] += a[m] * b;
            }
        }
        __syncthreads();
    }

    #pragma unroll
    for (int m = 0; m < 4; m++) {
        int r = m0 + ty * 4 + m;
        if (r >= n_rows) continue;
        if (routed) {
            int t = tok[r];
            float w = cw[r];
            float* orow = out + (size_t)t * H + n0;
            #pragma unroll
            for (int j = 0; j < 8; j++)
                atomicAdd(&orow[tx + 16 * j], w * c[m][j]);
        } else {
            float sg = g_sg[r];
            float* orow = out + (size_t)r * H + n0;
            #pragma unroll
            for (int j = 0; j < 8; j++)
                orow[tx + 16 * j] = sg * c[m][j];
        }
    }
}

// ---------------------------------------------------------------------------------
extern "C" void kernel_launch(void* const* d_in, const int* in_sizes, int n_in,
                              void* d_out, int out_size)
{
    (void)in_sizes; (void)n_in; (void)out_size;
    const float* x             = (const float*)d_in[0];
    const float* gate_w        = (const float*)d_in[1];
    const float* w_gate        = (const float*)d_in[2];
    const float* w_up          = (const float*)d_in[3];
    const float* w_down        = (const float*)d_in[4];
    const float* sw_gate       = (const float*)d_in[5];
    const float* sw_up         = (const float*)d_in[6];
    const float* sw_down       = (const float*)d_in[7];
    const float* shared_gate_w = (const float*)d_in[8];
    float* out = (float*)d_out;

    zero_cnt_kernel<<<1, 32>>>();
    router_kernel<<<T / 8, 256>>>(x, gate_w, shared_gate_w);
    scatter_kernel<<<T / 256, 256>>>();

    // shared expert: act then down-proj (plain stores initialize out)
    mlp_a_kernel<<<dim3(I / 128, T / 64, 1), 256>>>(x, sw_gate, sw_up, 0);
    mlp_b_kernel<<<dim3(H / 128, T / 64, 1), 256>>>(sw_down, out, 0);

    // routed experts: act then weighted atomic scatter-add
    mlp_a_kernel<<<dim3(I / 128, T / 64, E), 256>>>(x, w_gate, w_up, 1);
    mlp_b_kernel<<<dim3(H / 128, T / 64, E), 256>>>(w_down, out, 1);
}

// round 6
// speedup vs baseline: 2.1274x; 2.1274x over previous
#include <cuda_runtime.h>
#include <cuda_bf16.h>
#include <cstdint>
#include <math.h>

#define H 1024
#define I 1408
#define E 8
#define T 8192
#define KPA 3072            // 3*H packed K
#define KPB 4224            // 3*I packed K
#define KC  32              // K per chunk
#define NCA 96              // KPA/KC
#define NCB 132             // KPB/KC
#define NS  4               // pipeline stages

// smem: padded rows, 40 bf16 (80B) per 32-element row -> conflict-free ldmatrix
#define ROWB    80
#define MATB    10240       // 128 rows * 80B
#define STAGE_A (3*MATB)    // A + Bg + Bu
#define STAGE_B (2*MATB)    // A + B
#define SMEMA   (NS*STAGE_A + 512)
#define SMEMB   (NS*STAGE_B)

// ---------------- scratch (device globals) ----------------
__device__ __nv_bfloat16 g_xp  [(size_t)T*KPA];      // x packed  [hi|lo|hi]
__device__ __nv_bfloat16 g_wgp [(size_t)E*I*KPA];    // w_gate^T  [hi|hi|lo]
__device__ __nv_bfloat16 g_wup [(size_t)E*I*KPA];
__device__ __nv_bfloat16 g_wdp [(size_t)E*H*KPB];    // w_down^T  [hi|hi|lo]
__device__ __nv_bfloat16 g_swgp[(size_t)I*KPA];
__device__ __nv_bfloat16 g_swup[(size_t)I*KPA];
__device__ __nv_bfloat16 g_swdp[(size_t)H*KPB];
__device__ __nv_bfloat16 g_actp [(size_t)E*T*KPB];   // routed act packed [hi|lo|hi]
__device__ __nv_bfloat16 g_actps[(size_t)T*KPB];     // shared act packed
__device__ float g_eo[(size_t)E*T*H];                // raw routed expert outputs
__device__ int   g_tok[E*T];
__device__ int   g_cnt[E];
__device__ float g_sg [T];
__device__ int   g_ti [T*2];
__device__ float g_tw [T*2];
__device__ int   g_rowix[T*2];
__device__ float g_w2   [T*2];

// ---------------- asm helpers (all baseline sm_80+, safe for sm_100) ----------------
__device__ __forceinline__ uint32_t smem_u32(const void* p) {
    uint32_t a;
    asm("{ .reg .u64 t; cvta.to.shared.u64 t, %1; cvt.u32.u64 %0, t; }" : "=r"(a) : "l"(p));
    return a;
}
__device__ __forceinline__ void cp16(uint32_t s, const void* g) {
    asm volatile("cp.async.cg.shared.global [%0], [%1], 16;" :: "r"(s), "l"(g));
}
__device__ __forceinline__ void cp_commit() { asm volatile("cp.async.commit_group;" ::: "memory"); }
template<int N> __device__ __forceinline__ void cp_wait() {
    asm volatile("cp.async.wait_group %0;" :: "n"(N) : "memory");
}
#define LDSM4(r0,r1,r2,r3,addr) \
    asm volatile("ldmatrix.sync.aligned.m8n8.x4.shared.b16 {%0,%1,%2,%3}, [%4];" \
        : "=r"(r0),"=r"(r1),"=r"(r2),"=r"(r3) : "r"(addr))
#define LDSM2(r0,r1,addr) \
    asm volatile("ldmatrix.sync.aligned.m8n8.x2.shared.b16 {%0,%1}, [%2];" \
        : "=r"(r0),"=r"(r1) : "r"(addr))
#define MMA(d, a, b) \
    asm volatile("mma.sync.aligned.m16n8k16.row.col.f32.bf16.bf16.f32 " \
        "{%0,%1,%2,%3}, {%4,%5,%6,%7}, {%8,%9}, {%0,%1,%2,%3};" \
        : "+f"((d)[0]),"+f"((d)[1]),"+f"((d)[2]),"+f"((d)[3]) \
        : "r"((a)[0]),"r"((a)[1]),"r"((a)[2]),"r"((a)[3]), "r"((b)[0]),"r"((b)[1]))

__device__ __forceinline__ uint32_t pack2(float v0, float v1, uint32_t& lo2) {
    __nv_bfloat16 h0 = __float2bfloat16(v0), h1 = __float2bfloat16(v1);
    __nv_bfloat16 l0 = __float2bfloat16(v0 - __bfloat162float(h0));
    __nv_bfloat16 l1 = __float2bfloat16(v1 - __bfloat162float(h1));
    lo2 = (uint32_t)__bfloat16_as_ushort(l0) | ((uint32_t)__bfloat16_as_ushort(l1) << 16);
    return (uint32_t)__bfloat16_as_ushort(h0) | ((uint32_t)__bfloat16_as_ushort(h1) << 16);
}

// ---------------- router / scatter (proven in R1) ----------------
__global__ __launch_bounds__(256) void router_kernel(
    const float* __restrict__ x, const float* __restrict__ gate_w,
    const float* __restrict__ shared_gate_w)
{
    __shared__ float sgw[9][H];
    for (int idx = threadIdx.x; idx < 9 * H; idx += blockDim.x) {
        int e = idx / H, h = idx % H;
        sgw[e][h] = (e < 8) ? gate_w[idx] : shared_gate_w[h];
    }
    __syncthreads();
    int warp = threadIdx.x >> 5, lane = threadIdx.x & 31;
    int t = blockIdx.x * 8 + warp;
    const float4* xr = (const float4*)(x + (size_t)t * H);
    float acc[9];
    #pragma unroll
    for (int e = 0; e < 9; e++) acc[e] = 0.f;
    for (int c = lane; c < H / 4; c += 32) {
        float4 xv = xr[c];
        #pragma unroll
        for (int e = 0; e < 9; e++) {
            float4 gv = ((const float4*)sgw[e])[c];
            acc[e] += xv.x * gv.x + xv.y * gv.y + xv.z * gv.z + xv.w * gv.w;
        }
    }
    #pragma unroll
    for (int e = 0; e < 9; e++)
        #pragma unroll
        for (int o = 16; o > 0; o >>= 1)
            acc[e] += __shfl_xor_sync(0xffffffffu, acc[e], o);
    if (lane == 0) {
        float m = acc[0];
        #pragma unroll
        for (int e = 1; e < 8; e++) m = fmaxf(m, acc[e]);
        float p[8];
        #pragma unroll
        for (int e = 0; e < 8; e++) p[e] = __expf(acc[e] - m);
        int i0 = 0;
        #pragma unroll
        for (int e = 1; e < 8; e++) if (p[e] > p[i0]) i0 = e;
        int i1 = -1;
        #pragma unroll
        for (int e = 0; e < 8; e++) {
            if (e == i0) continue;
            if (i1 < 0 || p[e] > p[i1]) i1 = e;
        }
        float w0 = p[i0], w1 = p[i1], ws = w0 + w1;
        g_ti[t*2+0] = i0; g_tw[t*2+0] = w0/ws;
        g_ti[t*2+1] = i1; g_tw[t*2+1] = w1/ws;
        g_sg[t] = 1.f / (1.f + __expf(-acc[8]));
    }
}

__global__ void zero_cnt_kernel() { if (threadIdx.x < E) g_cnt[threadIdx.x] = 0; }

__global__ void scatter_kernel() {
    int t = blockIdx.x * blockDim.x + threadIdx.x;
    if (t >= T) return;
    #pragma unroll
    for (int k = 0; k < 2; k++) {
        int e = g_ti[t*2+k];
        int pos = atomicAdd(&g_cnt[e], 1);
        g_tok[e*T + pos] = t;
        g_rowix[t*2+k] = e*T + pos;
        g_w2[t*2+k] = g_tw[t*2+k];
    }
}

// ---------------- packing ----------------
__global__ __launch_bounds__(256) void pack_x_kernel(const float* __restrict__ x) {
    int t = blockIdx.x;
    const float2* xr = (const float2*)(x + (size_t)t * H);
    uint32_t* o = (uint32_t*)(g_xp + (size_t)t * KPA);
    #pragma unroll
    for (int q = 0; q < 2; q++) {
        int p = threadIdx.x + q * 256;
        float2 v = xr[p];
        uint32_t ll, hh = pack2(v.x, v.y, ll);
        o[p]        = hh;   // seg0 hi
        o[512 + p]  = ll;   // seg1 lo
        o[1024 + p] = hh;   // seg2 hi
    }
}

// transpose + pack weights: src[R][C] fp32 -> dst[C][3R] bf16 segs (hi|hi|lo)
__global__ __launch_bounds__(256) void pack_w_kernel(const float* __restrict__ src,
                                                     int R, int C, int sel)
{
    __nv_bfloat16* dst =
        sel == 0 ? g_wgp : sel == 1 ? g_wup : sel == 2 ? g_wdp :
        sel == 3 ? g_swgp : sel == 4 ? g_swup : g_swdp;
    size_t so = (size_t)blockIdx.z * R * C;
    size_t dofs = (size_t)blockIdx.z * C * 3 * R;
    __shared__ float tile[32][33];
    int tx = threadIdx.x & 31, tw = threadIdx.x >> 5;
    int r0 = blockIdx.y * 32, c0 = blockIdx.x * 32;
    #pragma unroll
    for (int q = 0; q < 4; q++) {
        int ty = tw + q * 8;
        tile[ty][tx] = src[so + (size_t)(r0 + ty) * C + c0 + tx];
    }
    __syncthreads();
    #pragma unroll
    for (int q = 0; q < 4; q++) {
        int ty = tw + q * 8;
        float v = tile[tx][ty];
        __nv_bfloat16 h = __float2bfloat16(v);
        __nv_bfloat16 l = __float2bfloat16(v - __bfloat162float(h));
        size_t b = dofs + (size_t)(c0 + ty) * 3 * R + (r0 + tx);
        dst[b]       = h;
        dst[b + R]   = h;
        dst[b + 2*R] = l;
    }
}

// -------- phase A: silu(x@Wg)*(x@Wu) via mma.sync bf16, fused re-split epilogue ------
__global__ __launch_bounds__(256, 1) void gemm_a_kernel(int routed) {
    int e = blockIdx.z;
    int n_rows;
    const __nv_bfloat16 *wg, *wu;
    __nv_bfloat16* act;
    const int* tok = nullptr;
    if (routed) {
        n_rows = g_cnt[e];
        wg = g_wgp + (size_t)e * I * KPA;
        wu = g_wup + (size_t)e * I * KPA;
        act = g_actp + (size_t)e * T * KPB;
        tok = g_tok + e * T;
    } else { n_rows = T; wg = g_swgp; wu = g_swup; act = g_actps; }
    int m0 = blockIdx.y * 128;
    if (m0 >= n_rows) return;
    int n0 = blockIdx.x * 128;

    extern __shared__ char smem[];
    uint32_t sb = smem_u32(smem);
    int* srow = (int*)(smem + NS*STAGE_A);
    int tid = threadIdx.x;
    int w = tid >> 5, l = tid & 31, wm = w >> 2, wn = w & 3;

    if (tid < 128) {
        int r = m0 + tid;
        srow[tid] = routed ? tok[(r < n_rows) ? r : (n_rows - 1)] : r;
    }
    __syncthreads();

    auto load_stage = [&](int s, int c) {
        int k0 = c * KC;
        uint32_t base = sb + s * STAGE_A;
        #pragma unroll
        for (int q = 0; q < 6; q++) {
            int o = tid + q * 256;
            int mat = o >> 9, idx = o & 511, r = idx >> 2, cc = idx & 3;
            uint32_t dst = base + mat * MATB + r * ROWB + cc * 16;
            const __nv_bfloat16* src =
                (mat == 0) ? g_xp + (size_t)srow[r] * KPA + k0 + cc * 8 :
                (mat == 1) ? wg + (size_t)(n0 + r) * KPA + k0 + cc * 8 :
                             wu + (size_t)(n0 + r) * KPA + k0 + cc * 8;
            cp16(dst, src);
        }
    };

    #pragma unroll
    for (int s = 0; s < NS - 1; s++) { load_stage(s, s); cp_commit(); }

    float accg[4][4][4] = {}, accu[4][4][4] = {};

    for (int i = 0; i < NCA; i++) {
        cp_wait<NS-2>();
        __syncthreads();
        uint32_t base = sb + (i & (NS-1)) * STAGE_A;
        #pragma unroll
        for (int ks = 0; ks < 2; ks++) {
            int kk = ks * 16;
            uint32_t afr[4][4];
            #pragma unroll
            for (int mf = 0; mf < 4; mf++) {
                uint32_t ad = base + (uint32_t)(wm*64 + mf*16 + (l & 15)) * ROWB
                            + (kk + ((l >> 4) << 3)) * 2;
                LDSM4(afr[mf][0], afr[mf][1], afr[mf][2], afr[mf][3], ad);
            }
            #pragma unroll
            for (int nf = 0; nf < 4; nf++) {
                uint32_t roff = (uint32_t)(wn*32 + nf*8 + (l & 7)) * ROWB
                              + (kk + ((l >> 3) & 1) * 8) * 2;
                uint32_t bg[2], bu[2];
                LDSM2(bg[0], bg[1], base + MATB + roff);
                LDSM2(bu[0], bu[1], base + 2*MATB + roff);
                #pragma unroll
                for (int mf = 0; mf < 4; mf++) {
                    MMA(accg[mf][nf], afr[mf], bg);
                    MMA(accu[mf][nf], afr[mf], bu);
                }
            }
        }
        __syncthreads();
        int nc = i + NS - 1;
        if (nc < NCA) load_stage(nc & (NS-1), nc);
        cp_commit();   // always commit (possibly empty) to keep wait invariant
    }

    // epilogue: silu(g)*u, re-split to [hi|lo|hi]
    #pragma unroll
    for (int mf = 0; mf < 4; mf++) {
        #pragma unroll
        for (int h2 = 0; h2 < 2; h2++) {
            int gr = m0 + wm*64 + mf*16 + (l >> 2) + h2*8;
            if (gr >= n_rows) continue;
            __nv_bfloat16* arow = act + (size_t)gr * KPB;
            #pragma unroll
            for (int nf = 0; nf < 4; nf++) {
                float g0 = accg[mf][nf][2*h2], g1 = accg[mf][nf][2*h2+1];
                float u0 = accu[mf][nf][2*h2], u1 = accu[mf][nf][2*h2+1];
                float v0 = g0 * u0 / (1.f + __expf(-g0));
                float v1 = g1 * u1 / (1.f + __expf(-g1));
                uint32_t ll, hh = pack2(v0, v1, ll);
                int col = n0 + wn*32 + nf*8 + (l & 3)*2;
                *(uint32_t*)(arow + col)       = hh;
                *(uint32_t*)(arow + I + col)   = ll;
                *(uint32_t*)(arow + 2*I + col) = hh;
            }
        }
    }
}

// -------- phase B: act @ Wd -> g_eo (routed) / out*sg (shared) ----------------------
__global__ __launch_bounds__(256, 2) void gemm_b_kernel(float* __restrict__ out, int routed) {
    int e = blockIdx.z;
    int n_rows;
    const __nv_bfloat16 *wd, *act;
    if (routed) {
        n_rows = g_cnt[e];
        wd = g_wdp + (size_t)e * H * KPB;
        act = g_actp + (size_t)e * T * KPB;
    } else { n_rows = T; wd = g_swdp; act = g_actps; }
    int m0 = blockIdx.y * 128;
    if (m0 >= n_rows) return;
    int n0 = blockIdx.x * 128;

    extern __shared__ char smem[];
    uint32_t sb = smem_u32(smem);
    int tid = threadIdx.x;
    int w = tid >> 5, l = tid & 31, wm = w >> 2, wn = w & 3;

    auto load_stage = [&](int s, int c) {
        int k0 = c * KC;
        uint32_t base = sb + s * STAGE_B;
        #pragma unroll
        for (int q = 0; q < 4; q++) {
            int o = tid + q * 256;
            int mat = o >> 9, idx = o & 511, r = idx >> 2, cc = idx & 3;
            uint32_t dst = base + mat * MATB + r * ROWB + cc * 16;
            const __nv_bfloat16* src =
                (mat == 0) ? act + (size_t)(m0 + r) * KPB + k0 + cc * 8
                           : wd + (size_t)(n0 + r) * KPB + k0 + cc * 8;
            cp16(dst, src);
        }
    };

    #pragma unroll
    for (int s = 0; s < NS - 1; s++) { load_stage(s, s); cp_commit(); }

    float acc[4][4][4] = {};

    for (int i = 0; i < NCB; i++) {
        cp_wait<NS-2>();
        __syncthreads();
        uint32_t base = sb + (i & (NS-1)) * STAGE_B;
        #pragma unroll
        for (int ks = 0; ks < 2; ks++) {
            int kk = ks * 16;
            uint32_t afr[4][4];
            #pragma unroll
            for (int mf = 0; mf < 4; mf++) {
                uint32_t ad = base + (uint32_t)(wm*64 + mf*16 + (l & 15)) * ROWB
                            + (kk + ((l >> 4) << 3)) * 2;
                LDSM4(afr[mf][0], afr[mf][1], afr[mf][2], afr[mf][3], ad);
            }
            #pragma unroll
            for (int nf = 0; nf < 4; nf++) {
                uint32_t roff = (uint32_t)(wn*32 + nf*8 + (l & 7)) * ROWB
                              + (kk + ((l >> 3) & 1) * 8) * 2;
                uint32_t bfr[2];
                LDSM2(bfr[0], bfr[1], base + MATB + roff);
                #pragma unroll
                for (int mf = 0; mf < 4; mf++)
                    MMA(acc[mf][nf], afr[mf], bfr);
            }
        }
        __syncthreads();
        int nc = i + NS - 1;
        if (nc < NCB) load_stage(nc & (NS-1), nc);
        cp_commit();
    }

    #pragma unroll
    for (int mf = 0; mf < 4; mf++) {
        #pragma unroll
        for (int h2 = 0; h2 < 2; h2++) {
            int gr = m0 + wm*64 + mf*16 + (l >> 2) + h2*8;
            if (gr >= n_rows) continue;
            int colb = n0 + wn*32 + (l & 3)*2;
            if (routed) {
                float* orow = g_eo + (size_t)(e * T + gr) * H;
                #pragma unroll
                for (int nf = 0; nf < 4; nf++)
                    *(float2*)(orow + colb + nf*8) =
                        make_float2(acc[mf][nf][2*h2], acc[mf][nf][2*h2+1]);
            } else {
                float sg = g_sg[gr];
                float* orow = out + (size_t)gr * H;
                #pragma unroll
                for (int nf = 0; nf < 4; nf++)
                    *(float2*)(orow + colb + nf*8) =
                        make_float2(sg * acc[mf][nf][2*h2], sg * acc[mf][nf][2*h2+1]);
            }
        }
    }
}

// ---------------- final combine: out += w0*eo[r0] + w1*eo[r1] ----------------
__global__ __launch_bounds__(256) void combine_kernel(float* __restrict__ out) {
    int t = blockIdx.x;
    int r0 = g_rowix[t*2], r1 = g_rowix[t*2+1];
    float w0 = g_w2[t*2], w1 = g_w2[t*2+1];
    const float4* a = (const float4*)(g_eo + (size_t)r0 * H);
    const float4* b = (const float4*)(g_eo + (size_t)r1 * H);
    float4* o = (float4*)(out + (size_t)t * H);
    int i = threadIdx.x;                       // H/4 = 256
    float4 ov = o[i], av = a[i], bv = b[i];
    ov.x += w0*av.x + w1*bv.x;
    ov.y += w0*av.y + w1*bv.y;
    ov.z += w0*av.z + w1*bv.z;
    ov.w += w0*av.w + w1*bv.w;
    o[i] = ov;
}

// ---------------------------------------------------------------------------------
extern "C" void kernel_launch(void* const* d_in, const int* in_sizes, int n_in,
                              void* d_out, int out_size)
{
    (void)in_sizes; (void)n_in; (void)out_size;
    const float* x             = (const float*)d_in[0];
    const float* gate_w        = (const float*)d_in[1];
    const float* w_gate        = (const float*)d_in[2];
    const float* w_up          = (const float*)d_in[3];
    const float* w_down        = (const float*)d_in[4];
    const float* sw_gate       = (const float*)d_in[5];
    const float* sw_up         = (const float*)d_in[6];
    const float* sw_down       = (const float*)d_in[7];
    const float* shared_gate_w = (const float*)d_in[8];
    float* out = (float*)d_out;

    cudaFuncSetAttribute(gemm_a_kernel, cudaFuncAttributeMaxDynamicSharedMemorySize, SMEMA);
    cudaFuncSetAttribute(gemm_b_kernel, cudaFuncAttributeMaxDynamicSharedMemorySize, SMEMB);

    zero_cnt_kernel<<<1, 32>>>();
    router_kernel<<<T / 8, 256>>>(x, gate_w, shared_gate_w);
    scatter_kernel<<<T / 256, 256>>>();

    pack_x_kernel<<<T, 256>>>(x);
    pack_w_kernel<<<dim3(I/32, H/32, E), 256>>>(w_gate, H, I, 0);
    pack_w_kernel<<<dim3(I/32, H/32, E), 256>>>(w_up,   H, I, 1);
    pack_w_kernel<<<dim3(H/32, I/32, E), 256>>>(w_down, I, H, 2);
    pack_w_kernel<<<dim3(I/32, H/32, 1), 256>>>(sw_gate, H, I, 3);
    pack_w_kernel<<<dim3(I/32, H/32, 1), 256>>>(sw_up,   H, I, 4);
    pack_w_kernel<<<dim3(H/32, I/32, 1), 256>>>(sw_down, I, H, 5);

    // shared expert (dense): act, then down-proj writing out with sigmoid gate
    gemm_a_kernel<<<dim3(I/128, T/128, 1), 256, SMEMA>>>(0);
    gemm_b_kernel<<<dim3(H/128, T/128, 1), 256, SMEMB>>>(out, 0);

    // routed experts: act, then raw down-proj into g_eo
    gemm_a_kernel<<<dim3(I/128, T/128, E), 256, SMEMA>>>(1);
    gemm_b_kernel<<<dim3(H/128, T/128, E), 256, SMEMB>>>(out, 1);

    // final weighted combine
    combine_kernel<<<T, 256>>>(out);
}

// round 8
// speedup vs baseline: 2.2985x; 1.0805x over previous
#include <cuda_runtime.h>
#include <cuda_bf16.h>
#include <cstdint>
#include <math.h>

#define H 1024
#define I 1408
#define E 8
#define T 8192
#define KPA 3072            // 3*H packed K
#define KPB 4224            // 3*I packed K
#define KC  64              // K per chunk
#define NCA 48              // KPA/KC
#define NCB 66              // KPB/KC
#define NS  3               // pipeline stages

// smem: padded rows, 72 bf16 (144B) per 64-element row -> conflict-free ldmatrix
#define ROWB    144
#define MATB    18432       // 128 rows * 144B
#define STAGE_A (3*MATB)    // A + Bg + Bu
#define STAGE_B (2*MATB)    // A + B
#define SMEMA   (NS*STAGE_A + 512)
#define SMEMB   (NS*STAGE_B)

// ---------------- scratch (device globals) ----------------
__device__ __nv_bfloat16 g_xp  [(size_t)T*KPA];      // x packed  [hi|lo|hi]
__device__ __nv_bfloat16 g_wgp [(size_t)E*I*KPA];    // w_gate^T  [hi|hi|lo]
__device__ __nv_bfloat16 g_wup [(size_t)E*I*KPA];
__device__ __nv_bfloat16 g_wdp [(size_t)E*H*KPB];    // w_down^T  [hi|hi|lo]
__device__ __nv_bfloat16 g_swgp[(size_t)I*KPA];
__device__ __nv_bfloat16 g_swup[(size_t)I*KPA];
__device__ __nv_bfloat16 g_swdp[(size_t)H*KPB];
__device__ __nv_bfloat16 g_actp [(size_t)E*T*KPB];   // routed act packed [hi|lo|hi]
__device__ __nv_bfloat16 g_actps[(size_t)T*KPB];     // shared act packed
__device__ int   g_tok[E*T];
__device__ float g_cw [E*T];
__device__ int   g_cnt[E];
__device__ float g_sg [T];
__device__ int   g_ti [T*2];
__device__ float g_tw [T*2];

// ---------------- asm helpers (all baseline sm_80+, safe for sm_100) ----------------
__device__ __forceinline__ uint32_t smem_u32(const void* p) {
    uint32_t a;
    asm("{ .reg .u64 t; cvta.to.shared.u64 t, %1; cvt.u32.u64 %0, t; }" : "=r"(a) : "l"(p));
    return a;
}
__device__ __forceinline__ void cp16(uint32_t s, const void* g) {
    asm volatile("cp.async.cg.shared.global [%0], [%1], 16;" :: "r"(s), "l"(g));
}
__device__ __forceinline__ void cp_commit() { asm volatile("cp.async.commit_group;" ::: "memory"); }
template<int N> __device__ __forceinline__ void cp_wait() {
    asm volatile("cp.async.wait_group %0;" :: "n"(N) : "memory");
}
#define LDSM4(r0,r1,r2,r3,addr) \
    asm volatile("ldmatrix.sync.aligned.m8n8.x4.shared.b16 {%0,%1,%2,%3}, [%4];" \
        : "=r"(r0),"=r"(r1),"=r"(r2),"=r"(r3) : "r"(addr))
#define LDSM2(r0,r1,addr) \
    asm volatile("ldmatrix.sync.aligned.m8n8.x2.shared.b16 {%0,%1}, [%2];" \
        : "=r"(r0),"=r"(r1) : "r"(addr))
#define MMA(d, a, b) \
    asm volatile("mma.sync.aligned.m16n8k16.row.col.f32.bf16.bf16.f32 " \
        "{%0,%1,%2,%3}, {%4,%5,%6,%7}, {%8,%9}, {%0,%1,%2,%3};" \
        : "+f"((d)[0]),"+f"((d)[1]),"+f"((d)[2]),"+f"((d)[3]) \
        : "r"((a)[0]),"r"((a)[1]),"r"((a)[2]),"r"((a)[3]), "r"((b)[0]),"r"((b)[1]))

__device__ __forceinline__ uint32_t pack2(float v0, float v1, uint32_t& lo2) {
    __nv_bfloat16 h0 = __float2bfloat16(v0), h1 = __float2bfloat16(v1);
    __nv_bfloat16 l0 = __float2bfloat16(v0 - __bfloat162float(h0));
    __nv_bfloat16 l1 = __float2bfloat16(v1 - __bfloat162float(h1));
    lo2 = (uint32_t)__bfloat16_as_ushort(l0) | ((uint32_t)__bfloat16_as_ushort(l1) << 16);
    return (uint32_t)__bfloat16_as_ushort(h0) | ((uint32_t)__bfloat16_as_ushort(h1) << 16);
}

// ---------------- router / scatter ----------------
__global__ __launch_bounds__(256) void router_kernel(
    const float* __restrict__ x, const float* __restrict__ gate_w,
    const float* __restrict__ shared_gate_w)
{
    __shared__ float sgw[9][H];
    for (int idx = threadIdx.x; idx < 9 * H; idx += blockDim.x) {
        int e = idx / H, h = idx % H;
        sgw[e][h] = (e < 8) ? gate_w[idx] : shared_gate_w[h];
    }
    __syncthreads();
    int warp = threadIdx.x >> 5, lane = threadIdx.x & 31;
    int t = blockIdx.x * 8 + warp;
    const float4* xr = (const float4*)(x + (size_t)t * H);
    float acc[9];
    #pragma unroll
    for (int e = 0; e < 9; e++) acc[e] = 0.f;
    for (int c = lane; c < H / 4; c += 32) {
        float4 xv = xr[c];
        #pragma unroll
        for (int e = 0; e < 9; e++) {
            float4 gv = ((const float4*)sgw[e])[c];
            acc[e] += xv.x * gv.x + xv.y * gv.y + xv.z * gv.z + xv.w * gv.w;
        }
    }
    #pragma unroll
    for (int e = 0; e < 9; e++)
        #pragma unroll
        for (int o = 16; o > 0; o >>= 1)
            acc[e] += __shfl_xor_sync(0xffffffffu, acc[e], o);
    if (lane == 0) {
        float m = acc[0];
        #pragma unroll
        for (int e = 1; e < 8; e++) m = fmaxf(m, acc[e]);
        float p[8];
        #pragma unroll
        for (int e = 0; e < 8; e++) p[e] = __expf(acc[e] - m);
        int i0 = 0;
        #pragma unroll
        for (int e = 1; e < 8; e++) if (p[e] > p[i0]) i0 = e;
        int i1 = -1;
        #pragma unroll
        for (int e = 0; e < 8; e++) {
            if (e == i0) continue;
            if (i1 < 0 || p[e] > p[i1]) i1 = e;
        }
        float w0 = p[i0], w1 = p[i1], ws = w0 + w1;
        g_ti[t*2+0] = i0; g_tw[t*2+0] = w0/ws;
        g_ti[t*2+1] = i1; g_tw[t*2+1] = w1/ws;
        g_sg[t] = 1.f / (1.f + __expf(-acc[8]));
    }
}

__global__ void zero_cnt_kernel() { if (threadIdx.x < E) g_cnt[threadIdx.x] = 0; }

__global__ void scatter_kernel() {
    int t = blockIdx.x * blockDim.x + threadIdx.x;
    if (t >= T) return;
    #pragma unroll
    for (int k = 0; k < 2; k++) {
        int e = g_ti[t*2+k];
        int pos = atomicAdd(&g_cnt[e], 1);
        g_tok[e*T + pos] = t;
        g_cw [e*T + pos] = g_tw[t*2+k];
    }
}

// ---------------- packing ----------------
__global__ __launch_bounds__(256) void pack_x_kernel(const float* __restrict__ x) {
    int t = blockIdx.x;
    const float2* xr = (const float2*)(x + (size_t)t * H);
    uint32_t* o = (uint32_t*)(g_xp + (size_t)t * KPA);
    #pragma unroll
    for (int q = 0; q < 2; q++) {
        int p = threadIdx.x + q * 256;
        float2 v = xr[p];
        uint32_t ll, hh = pack2(v.x, v.y, ll);
        o[p]        = hh;   // seg0 hi
        o[512 + p]  = ll;   // seg1 lo
        o[1024 + p] = hh;   // seg2 hi
    }
}

// transpose + pack weights: src[R][C] fp32 -> dst[C][3R] bf16 segs (hi|hi|lo)
__global__ __launch_bounds__(256) void pack_w_kernel(const float* __restrict__ src,
                                                     int R, int C, int sel)
{
    __nv_bfloat16* dst =
        sel == 0 ? g_wgp : sel == 1 ? g_wup : sel == 2 ? g_wdp :
        sel == 3 ? g_swgp : sel == 4 ? g_swup : g_swdp;
    size_t so = (size_t)blockIdx.z * R * C;
    size_t dofs = (size_t)blockIdx.z * C * 3 * R;
    __shared__ float tile[32][33];
    int tx = threadIdx.x & 31, tw = threadIdx.x >> 5;
    int r0 = blockIdx.y * 32, c0 = blockIdx.x * 32;
    #pragma unroll
    for (int q = 0; q < 4; q++) {
        int ty = tw + q * 8;
        tile[ty][tx] = src[so + (size_t)(r0 + ty) * C + c0 + tx];
    }
    __syncthreads();
    #pragma unroll
    for (int q = 0; q < 4; q++) {
        int ty = tw + q * 8;
        float v = tile[tx][ty];
        __nv_bfloat16 h = __float2bfloat16(v);
        __nv_bfloat16 l = __float2bfloat16(v - __bfloat162float(h));
        size_t b = dofs + (size_t)(c0 + ty) * 3 * R + (r0 + tx);
        dst[b]       = h;
        dst[b + R]   = h;
        dst[b + 2*R] = l;
    }
}

// -------- phase A: silu(x@Wg)*(x@Wu) via mma.sync bf16, fused re-split epilogue ------
__global__ __launch_bounds__(256, 1) void gemm_a_kernel(int routed) {
    int e = blockIdx.z;
    int n_rows;
    const __nv_bfloat16 *wg, *wu;
    __nv_bfloat16* act;
    const int* tok = nullptr;
    if (routed) {
        n_rows = g_cnt[e];
        wg = g_wgp + (size_t)e * I * KPA;
        wu = g_wup + (size_t)e * I * KPA;
        act = g_actp + (size_t)e * T * KPB;
        tok = g_tok + e * T;
    } else { n_rows = T; wg = g_swgp; wu = g_swup; act = g_actps; }
    int m0 = blockIdx.y * 128;
    if (m0 >= n_rows) return;
    int n0 = blockIdx.x * 128;

    extern __shared__ char smem[];
    uint32_t sb = smem_u32(smem);
    int* srow = (int*)(smem + NS*STAGE_A);
    int tid = threadIdx.x;
    int w = tid >> 5, l = tid & 31, wm = w >> 2, wn = w & 3;

    if (tid < 128) {
        int r = m0 + tid;
        srow[tid] = routed ? tok[(r < n_rows) ? r : (n_rows - 1)] : r;
    }
    __syncthreads();

    auto load_stage = [&](int s, int c) {
        int k0 = c * KC;
        uint32_t base = sb + s * STAGE_A;
        #pragma unroll
        for (int q = 0; q < 12; q++) {
            int o = tid + q * 256;
            int mat = o >> 10, idx = o & 1023, r = idx >> 3, cc = idx & 7;
            uint32_t dst = base + mat * MATB + r * ROWB + cc * 16;
            const __nv_bfloat16* src =
                (mat == 0) ? g_xp + (size_t)srow[r] * KPA + k0 + cc * 8 :
                (mat == 1) ? wg + (size_t)(n0 + r) * KPA + k0 + cc * 8 :
                             wu + (size_t)(n0 + r) * KPA + k0 + cc * 8;
            cp16(dst, src);
        }
    };

    #pragma unroll
    for (int s = 0; s < NS - 1; s++) { load_stage(s, s); cp_commit(); }

    float accg[4][4][4] = {}, accu[4][4][4] = {};

    for (int i = 0; i < NCA; i++) {
        cp_wait<NS-2>();
        __syncthreads();
        uint32_t base = sb + (i % NS) * STAGE_A;
        #pragma unroll
        for (int ks = 0; ks < 4; ks++) {
            int kk = ks * 16;
            uint32_t afr[4][4];
            #pragma unroll
            for (int mf = 0; mf < 4; mf++) {
                uint32_t ad = base + (uint32_t)(wm*64 + mf*16 + (l & 15)) * ROWB
                            + (kk + ((l >> 4) << 3)) * 2;
                LDSM4(afr[mf][0], afr[mf][1], afr[mf][2], afr[mf][3], ad);
            }
            #pragma unroll
            for (int nf = 0; nf < 4; nf++) {
                uint32_t roff = (uint32_t)(wn*32 + nf*8 + (l & 7)) * ROWB
                              + (kk + ((l >> 3) & 1) * 8) * 2;
                uint32_t bg[2], bu[2];
                LDSM2(bg[0], bg[1], base + MATB + roff);
                LDSM2(bu[0], bu[1], base + 2*MATB + roff);
                #pragma unroll
                for (int mf = 0; mf < 4; mf++) {
                    MMA(accg[mf][nf], afr[mf], bg);
                    MMA(accu[mf][nf], afr[mf], bu);
                }
            }
        }
        __syncthreads();
        int nc = i + NS - 1;
        if (nc < NCA) load_stage(nc % NS, nc);
        cp_commit();   // always commit (possibly empty) to keep wait invariant
    }

    // epilogue: silu(g)*u, re-split to [hi|lo|hi]
    #pragma unroll
    for (int mf = 0; mf < 4; mf++) {
        #pragma unroll
        for (int h2 = 0; h2 < 2; h2++) {
            int gr = m0 + wm*64 + mf*16 + (l >> 2) + h2*8;
            if (gr >= n_rows) continue;
            __nv_bfloat16* arow = act + (size_t)gr * KPB;
            #pragma unroll
            for (int nf = 0; nf < 4; nf++) {
                float g0 = accg[mf][nf][2*h2], g1 = accg[mf][nf][2*h2+1];
                float u0 = accu[mf][nf][2*h2], u1 = accu[mf][nf][2*h2+1];
                float v0 = g0 * u0 / (1.f + __expf(-g0));
                float v1 = g1 * u1 / (1.f + __expf(-g1));
                uint32_t ll, hh = pack2(v0, v1, ll);
                int col = n0 + wn*32 + nf*8 + (l & 3)*2;
                *(uint32_t*)(arow + col)       = hh;
                *(uint32_t*)(arow + I + col)   = ll;
                *(uint32_t*)(arow + 2*I + col) = hh;
            }
        }
    }
}

// -------- phase B: act @ Wd; routed: out += cw*acc (atomic); shared: out = sg*acc ----
__global__ __launch_bounds__(256, 1) void gemm_b_kernel(float* __restrict__ out, int routed) {
    int e = blockIdx.z;
    int n_rows;
    const __nv_bfloat16 *wd, *act;
    if (routed) {
        n_rows = g_cnt[e];
        wd = g_wdp + (size_t)e * H * KPB;
        act = g_actp + (size_t)e * T * KPB;
    } else { n_rows = T; wd = g_swdp; act = g_actps; }
    int m0 = blockIdx.y * 128;
    if (m0 >= n_rows) return;
    int n0 = blockIdx.x * 128;

    extern __shared__ char smem[];
    uint32_t sb = smem_u32(smem);
    int tid = threadIdx.x;
    int w = tid >> 5, l = tid & 31, wm = w >> 2, wn = w & 3;

    auto load_stage = [&](int s, int c) {
        int k0 = c * KC;
        uint32_t base = sb + s * STAGE_B;
        #pragma unroll
        for (int q = 0; q < 8; q++) {
            int o = tid + q * 256;
            int mat = o >> 10, idx = o & 1023, r = idx >> 3, cc = idx & 7;
            uint32_t dst = base + mat * MATB + r * ROWB + cc * 16;
            const __nv_bfloat16* src =
                (mat == 0) ? act + (size_t)(m0 + r) * KPB + k0 + cc * 8
                           : wd + (size_t)(n0 + r) * KPB + k0 + cc * 8;
            cp16(dst, src);
        }
    };

    #pragma unroll
    for (int s = 0; s < NS - 1; s++) { load_stage(s, s); cp_commit(); }

    float acc[4][4][4] = {};

    for (int i = 0; i < NCB; i++) {
        cp_wait<NS-2>();
        __syncthreads();
        uint32_t base = sb + (i % NS) * STAGE_B;
        #pragma unroll
        for (int ks = 0; ks < 4; ks++) {
            int kk = ks * 16;
            uint32_t afr[4][4];
            #pragma unroll
            for (int mf = 0; mf < 4; mf++) {
                uint32_t ad = base + (uint32_t)(wm*64 + mf*16 + (l & 15)) * ROWB
                            + (kk + ((l >> 4) << 3)) * 2;
                LDSM4(afr[mf][0], afr[mf][1], afr[mf][2], afr[mf][3], ad);
            }
            #pragma unroll
            for (int nf = 0; nf < 4; nf++) {
                uint32_t roff = (uint32_t)(wn*32 + nf*8 + (l & 7)) * ROWB
                              + (kk + ((l >> 3) & 1) * 8) * 2;
                uint32_t bfr[2];
                LDSM2(bfr[0], bfr[1], base + MATB + roff);
                #pragma unroll
                for (int mf = 0; mf < 4; mf++)
                    MMA(acc[mf][nf], afr[mf], bfr);
            }
        }
        __syncthreads();
        int nc = i + NS - 1;
        if (nc < NCB) load_stage(nc % NS, nc);
        cp_commit();
    }

    #pragma unroll
    for (int mf = 0; mf < 4; mf++) {
        #pragma unroll
        for (int h2 = 0; h2 < 2; h2++) {
            int gr = m0 + wm*64 + mf*16 + (l >> 2) + h2*8;
            if (gr >= n_rows) continue;
            int colb = n0 + wn*32 + (l & 3)*2;
            if (routed) {
                int t = g_tok[e*T + gr];
                float cwv = g_cw[e*T + gr];
                float* orow = out + (size_t)t * H;
                #pragma unroll
                for (int nf = 0; nf < 4; nf++) {
                    atomicAdd(orow + colb + nf*8,     cwv * acc[mf][nf][2*h2]);
                    atomicAdd(orow + colb + nf*8 + 1, cwv * acc[mf][nf][2*h2+1]);
                }
            } else {
                float sg = g_sg[gr];
                float* orow = out + (size_t)gr * H;
                #pragma unroll
                for (int nf = 0; nf < 4; nf++)
                    *(float2*)(orow + colb + nf*8) =
                        make_float2(sg * acc[mf][nf][2*h2], sg * acc[mf][nf][2*h2+1]);
            }
        }
    }
}

// ---------------------------------------------------------------------------------
extern "C" void kernel_launch(void* const* d_in, const int* in_sizes, int n_in,
                              void* d_out, int out_size)
{
    (void)in_sizes; (void)n_in; (void)out_size;
    const float* x             = (const float*)d_in[0];
    const float* gate_w        = (const float*)d_in[1];
    const float* w_gate        = (const float*)d_in[2];
    const float* w_up          = (const float*)d_in[3];
    const float* w_down        = (const float*)d_in[4];
    const float* sw_gate       = (const float*)d_in[5];
    const float* sw_up         = (const float*)d_in[6];
    const float* sw_down       = (const float*)d_in[7];
    const float* shared_gate_w = (const float*)d_in[8];
    float* out = (float*)d_out;

    cudaFuncSetAttribute(gemm_a_kernel, cudaFuncAttributeMaxDynamicSharedMemorySize, SMEMA);
    cudaFuncSetAttribute(gemm_b_kernel, cudaFuncAttributeMaxDynamicSharedMemorySize, SMEMB);

    zero_cnt_kernel<<<1, 32>>>();
    router_kernel<<<T / 8, 256>>>(x, gate_w, shared_gate_w);
    scatter_kernel<<<T / 256, 256>>>();

    pack_x_kernel<<<T, 256>>>(x);
    pack_w_kernel<<<dim3(I/32, H/32, E), 256>>>(w_gate, H, I, 0);
    pack_w_kernel<<<dim3(I/32, H/32, E), 256>>>(w_up,   H, I, 1);
    pack_w_kernel<<<dim3(H/32, I/32, E), 256>>>(w_down, I, H, 2);
    pack_w_kernel<<<dim3(I/32, H/32, 1), 256>>>(sw_gate, H, I, 3);
    pack_w_kernel<<<dim3(I/32, H/32, 1), 256>>>(sw_up,   H, I, 4);
    pack_w_kernel<<<dim3(H/32, I/32, 1), 256>>>(sw_down, I, H, 5);

    // shared expert first: plain stores initialize `out`
    gemm_a_kernel<<<dim3(I/128, T/128, 1), 256, SMEMA>>>(0);
    gemm_b_kernel<<<dim3(H/128, T/128, 1), 256, SMEMB>>>(out, 0);

    // routed experts: act, then weighted atomicAdd into out
    gemm_a_kernel<<<dim3(I/128, T/128, E), 256, SMEMA>>>(1);
    gemm_b_kernel<<<dim3(H/128, T/128, E), 256, SMEMB>>>(out, 1);
}

// round 12
// speedup vs baseline: 2.4583x; 1.0695x over previous
#include <cuda_runtime.h>
#include <cuda_bf16.h>
#include <cstdint>
#include <math.h>

#define H 1024
#define I 1408
#define E 8
#define T 8192
#define KPA 3072            // 3*H packed K
#define KPB 4224            // 3*I packed K
#define KC  64              // K per chunk
#define NCA 48              // KPA/KC
#define NCB 66              // KPB/KC
#define NS  3               // pipeline stages

// smem: padded rows, 72 bf16 (144B) per 64-element row -> conflict-free ldmatrix
#define ROWB    144
#define MATB    18432       // 128 rows * 144B
#define STAGE_A (3*MATB)    // A + Bg + Bu
#define STAGE_B (2*MATB)    // A + B
#define SMEMA   (NS*STAGE_A + 512)
#define SMEMB   (NS*STAGE_B)

// ---------------- scratch (device globals) ----------------
__device__ __nv_bfloat16 g_xp  [(size_t)T*KPA];      // x packed  [hi|lo|hi]
__device__ __nv_bfloat16 g_wgp [(size_t)E*I*KPA];    // w_gate^T  [hi|hi|lo]
__device__ __nv_bfloat16 g_wup [(size_t)E*I*KPA];
__device__ __nv_bfloat16 g_wdp [(size_t)E*H*KPB];    // w_down^T  [hi|hi|lo]
__device__ __nv_bfloat16 g_swgp[(size_t)I*KPA];
__device__ __nv_bfloat16 g_swup[(size_t)I*KPA];
__device__ __nv_bfloat16 g_swdp[(size_t)H*KPB];
__device__ __nv_bfloat16 g_actp [(size_t)E*T*KPB];   // routed act packed [hi|lo|hi]
__device__ __nv_bfloat16 g_actps[(size_t)T*KPB];     // shared act packed
__device__ int   g_tok[E*T];
__device__ float g_cw [E*T];
__device__ int   g_cnt[E];
__device__ float g_sg [T];
__device__ int   g_ti [T*2];
__device__ float g_tw [T*2];

// ---------------- asm helpers (all baseline sm_80+, safe for sm_100) ----------------
__device__ __forceinline__ uint32_t smem_u32(const void* p) {
    uint32_t a;
    asm("{ .reg .u64 t; cvta.to.shared.u64 t, %1; cvt.u32.u64 %0, t; }" : "=r"(a) : "l"(p));
    return a;
}
__device__ __forceinline__ void cp16(uint32_t s, const void* g) {
    asm volatile("cp.async.cg.shared.global [%0], [%1], 16;" :: "r"(s), "l"(g));
}
__device__ __forceinline__ void cp_commit() { asm volatile("cp.async.commit_group;" ::: "memory"); }
template<int N> __device__ __forceinline__ void cp_wait() {
    asm volatile("cp.async.wait_group %0;" :: "n"(N) : "memory");
}
#define LDSM4(r0,r1,r2,r3,addr) \
    asm volatile("ldmatrix.sync.aligned.m8n8.x4.shared.b16 {%0,%1,%2,%3}, [%4];" \
        : "=r"(r0),"=r"(r1),"=r"(r2),"=r"(r3) : "r"(addr))
#define LDSM2(r0,r1,addr) \
    asm volatile("ldmatrix.sync.aligned.m8n8.x2.shared.b16 {%0,%1}, [%2];" \
        : "=r"(r0),"=r"(r1) : "r"(addr))
#define MMA(d, a, b) \
    asm volatile("mma.sync.aligned.m16n8k16.row.col.f32.bf16.bf16.f32 " \
        "{%0,%1,%2,%3}, {%4,%5,%6,%7}, {%8,%9}, {%0,%1,%2,%3};" \
        : "+f"((d)[0]),"+f"((d)[1]),"+f"((d)[2]),"+f"((d)[3]) \
        : "r"((a)[0]),"r"((a)[1]),"r"((a)[2]),"r"((a)[3]), "r"((b)[0]),"r"((b)[1]))

__device__ __forceinline__ uint32_t pack2(float v0, float v1, uint32_t& lo2) {
    __nv_bfloat16 h0 = __float2bfloat16(v0), h1 = __float2bfloat16(v1);
    __nv_bfloat16 l0 = __float2bfloat16(v0 - __bfloat162float(h0));
    __nv_bfloat16 l1 = __float2bfloat16(v1 - __bfloat162float(h1));
    lo2 = (uint32_t)__bfloat16_as_ushort(l0) | ((uint32_t)__bfloat16_as_ushort(l1) << 16);
    return (uint32_t)__bfloat16_as_ushort(h0) | ((uint32_t)__bfloat16_as_ushort(h1) << 16);
}

// ---------------- router / scatter ----------------
__global__ __launch_bounds__(256) void router_kernel(
    const float* __restrict__ x, const float* __restrict__ gate_w,
    const float* __restrict__ shared_gate_w)
{
    __shared__ float sgw[9][H];
    for (int idx = threadIdx.x; idx < 9 * H; idx += blockDim.x) {
        int e = idx / H, h = idx % H;
        sgw[e][h] = (e < 8) ? gate_w[idx] : shared_gate_w[h];
    }
    __syncthreads();
    int warp = threadIdx.x >> 5, lane = threadIdx.x & 31;
    int t = blockIdx.x * 8 + warp;
    const float4* xr = (const float4*)(x + (size_t)t * H);
    float acc[9];
    #pragma unroll
    for (int e = 0; e < 9; e++) acc[e] = 0.f;
    for (int c = lane; c < H / 4; c += 32) {
        float4 xv = xr[c];
        #pragma unroll
        for (int e = 0; e < 9; e++) {
            float4 gv = ((const float4*)sgw[e])[c];
            acc[e] += xv.x * gv.x + xv.y * gv.y + xv.z * gv.z + xv.w * gv.w;
        }
    }
    #pragma unroll
    for (int e = 0; e < 9; e++)
        #pragma unroll
        for (int o = 16; o > 0; o >>= 1)
            acc[e] += __shfl_xor_sync(0xffffffffu, acc[e], o);
    if (lane == 0) {
        float m = acc[0];
        #pragma unroll
        for (int e = 1; e < 8; e++) m = fmaxf(m, acc[e]);
        float p[8];
        #pragma unroll
        for (int e = 0; e < 8; e++) p[e] = __expf(acc[e] - m);
        int i0 = 0;
        #pragma unroll
        for (int e = 1; e < 8; e++) if (p[e] > p[i0]) i0 = e;
        int i1 = -1;
        #pragma unroll
        for (int e = 0; e < 8; e++) {
            if (e == i0) continue;
            if (i1 < 0 || p[e] > p[i1]) i1 = e;
        }
        float w0 = p[i0], w1 = p[i1], ws = w0 + w1;
        g_ti[t*2+0] = i0; g_tw[t*2+0] = w0/ws;
        g_ti[t*2+1] = i1; g_tw[t*2+1] = w1/ws;
        g_sg[t] = 1.f / (1.f + __expf(-acc[8]));
    }
}

__global__ void zero_cnt_kernel() { if (threadIdx.x < E) g_cnt[threadIdx.x] = 0; }

__global__ void scatter_kernel() {
    int t = blockIdx.x * blockDim.x + threadIdx.x;
    if (t >= T) return;
    #pragma unroll
    for (int k = 0; k < 2; k++) {
        int e = g_ti[t*2+k];
        int pos = atomicAdd(&g_cnt[e], 1);
        g_tok[e*T + pos] = t;
        g_cw [e*T + pos] = g_tw[t*2+k];
    }
}

// ---------------- packing ----------------
__global__ __launch_bounds__(256) void pack_x_kernel(const float* __restrict__ x) {
    int t = blockIdx.x;
    const float2* xr = (const float2*)(x + (size_t)t * H);
    uint32_t* o = (uint32_t*)(g_xp + (size_t)t * KPA);
    #pragma unroll
    for (int q = 0; q < 2; q++) {
        int p = threadIdx.x + q * 256;
        float2 v = xr[p];
        uint32_t ll, hh = pack2(v.x, v.y, ll);
        o[p]        = hh;   // seg0 hi
        o[512 + p]  = ll;   // seg1 lo
        o[1024 + p] = hh;   // seg2 hi
    }
}

// transpose + pack weights: src[R][C] fp32 -> dst[C][3R] bf16 segs (hi|hi|lo)
__global__ __launch_bounds__(256) void pack_w_kernel(const float* __restrict__ src,
                                                     int R, int C, int sel)
{
    __nv_bfloat16* dst =
        sel == 0 ? g_wgp : sel == 1 ? g_wup : sel == 2 ? g_wdp :
        sel == 3 ? g_swgp : sel == 4 ? g_swup : g_swdp;
    size_t so = (size_t)blockIdx.z * R * C;
    size_t dofs = (size_t)blockIdx.z * C * 3 * R;
    __shared__ float tile[32][33];
    int tx = threadIdx.x & 31, tw = threadIdx.x >> 5;
    int r0 = blockIdx.y * 32, c0 = blockIdx.x * 32;
    #pragma unroll
    for (int q = 0; q < 4; q++) {
        int ty = tw + q * 8;
        tile[ty][tx] = src[so + (size_t)(r0 + ty) * C + c0 + tx];
    }
    __syncthreads();
    #pragma unroll
    for (int q = 0; q < 4; q++) {
        int ty = tw + q * 8;
        float v = tile[tx][ty];
        __nv_bfloat16 h = __float2bfloat16(v);
        __nv_bfloat16 l = __float2bfloat16(v - __bfloat162float(h));
        size_t b = dofs + (size_t)(c0 + ty) * 3 * R + (r0 + tx);
        dst[b]       = h;
        dst[b + R]   = h;
        dst[b + 2*R] = l;
    }
}

// -------- phase A: silu(x@Wg)*(x@Wu) via mma.sync bf16, fused re-split epilogue ------
__global__ __launch_bounds__(256, 1) void gemm_a_kernel(int routed) {
    int e = blockIdx.z;
    int n_rows;
    const __nv_bfloat16 *wg, *wu;
    __nv_bfloat16* act;
    const int* tok = nullptr;
    if (routed) {
        n_rows = g_cnt[e];
        wg = g_wgp + (size_t)e * I * KPA;
        wu = g_wup + (size_t)e * I * KPA;
        act = g_actp + (size_t)e * T * KPB;
        tok = g_tok + e * T;
    } else { n_rows = T; wg = g_swgp; wu = g_swup; act = g_actps; }
    int m0 = blockIdx.y * 128;
    if (m0 >= n_rows) return;
    int n0 = blockIdx.x * 128;

    extern __shared__ char smem[];
    uint32_t sb = smem_u32(smem);
    int* srow = (int*)(smem + NS*STAGE_A);
    int tid = threadIdx.x;
    int w = tid >> 5, l = tid & 31, wm = w >> 2, wn = w & 3;

    if (tid < 128) {
        int r = m0 + tid;
        srow[tid] = routed ? tok[(r < n_rows) ? r : (n_rows - 1)] : r;
    }
    __syncthreads();

    auto load_stage = [&](int s, int c) {
        int k0 = c * KC;
        uint32_t base = sb + s * STAGE_A;
        #pragma unroll
        for (int q = 0; q < 12; q++) {
            int o = tid + q * 256;
            int mat = o >> 10, idx = o & 1023, r = idx >> 3, cc = idx & 7;
            uint32_t dst = base + mat * MATB + r * ROWB + cc * 16;
            const __nv_bfloat16* src =
                (mat == 0) ? g_xp + (size_t)srow[r] * KPA + k0 + cc * 8 :
                (mat == 1) ? wg + (size_t)(n0 + r) * KPA + k0 + cc * 8 :
                             wu + (size_t)(n0 + r) * KPA + k0 + cc * 8;
            cp16(dst, src);
        }
    };

    #pragma unroll
    for (int s = 0; s < NS - 1; s++) { load_stage(s, s); cp_commit(); }

    float accg[4][4][4] = {}, accu[4][4][4] = {};

    for (int i = 0; i < NCA; i++) {
        cp_wait<NS-2>();
        __syncthreads();
        uint32_t base = sb + (i % NS) * STAGE_A;
        #pragma unroll
        for (int ks = 0; ks < 4; ks++) {
            int kk = ks * 16;
            uint32_t afr[4][4];
            #pragma unroll
            for (int mf = 0; mf < 4; mf++) {
                uint32_t ad = base + (uint32_t)(wm*64 + mf*16 + (l & 15)) * ROWB
                            + (kk + ((l >> 4) << 3)) * 2;
                LDSM4(afr[mf][0], afr[mf][1], afr[mf][2], afr[mf][3], ad);
            }
            #pragma unroll
            for (int nf = 0; nf < 4; nf++) {
                uint32_t roff = (uint32_t)(wn*32 + nf*8 + (l & 7)) * ROWB
                              + (kk + ((l >> 3) & 1) * 8) * 2;
                uint32_t bg[2], bu[2];
                LDSM2(bg[0], bg[1], base + MATB + roff);
                LDSM2(bu[0], bu[1], base + 2*MATB + roff);
                #pragma unroll
                for (int mf = 0; mf < 4; mf++) {
                    MMA(accg[mf][nf], afr[mf], bg);
                    MMA(accu[mf][nf], afr[mf], bu);
                }
            }
        }
        __syncthreads();
        int nc = i + NS - 1;
        if (nc < NCA) load_stage(nc % NS, nc);
        cp_commit();   // always commit (possibly empty) to keep wait invariant
    }

    // epilogue: silu(g)*u, re-split to [hi|lo|hi]
    #pragma unroll
    for (int mf = 0; mf < 4; mf++) {
        #pragma unroll
        for (int h2 = 0; h2 < 2; h2++) {
            int gr = m0 + wm*64 + mf*16 + (l >> 2) + h2*8;
            if (gr >= n_rows) continue;
            __nv_bfloat16* arow = act + (size_t)gr * KPB;
            #pragma unroll
            for (int nf = 0; nf < 4; nf++) {
                float g0 = accg[mf][nf][2*h2], g1 = accg[mf][nf][2*h2+1];
                float u0 = accu[mf][nf][2*h2], u1 = accu[mf][nf][2*h2+1];
                float v0 = g0 * u0 / (1.f + __expf(-g0));
                float v1 = g1 * u1 / (1.f + __expf(-g1));
                uint32_t ll, hh = pack2(v0, v1, ll);
                int col = n0 + wn*32 + nf*8 + (l & 3)*2;
                *(uint32_t*)(arow + col)       = hh;
                *(uint32_t*)(arow + I + col)   = ll;
                *(uint32_t*)(arow + 2*I + col) = hh;
            }
        }
    }
}

// -------- phase B: act @ Wd; routed: out += cw*acc (atomic); shared: out = sg*acc ----
__global__ __launch_bounds__(256, 2) void gemm_b_kernel(float* __restrict__ out, int routed) {
    int e = blockIdx.z;
    int n_rows;
    const __nv_bfloat16 *wd, *act;
    if (routed) {
        n_rows = g_cnt[e];
        wd = g_wdp + (size_t)e * H * KPB;
        act = g_actp + (size_t)e * T * KPB;
    } else { n_rows = T; wd = g_swdp; act = g_actps; }
    int m0 = blockIdx.y * 128;
    if (m0 >= n_rows) return;
    int n0 = blockIdx.x * 128;

    extern __shared__ char smem[];
    uint32_t sb = smem_u32(smem);
    int tid = threadIdx.x;
    int w = tid >> 5, l = tid & 31, wm = w >> 2, wn = w & 3;

    auto load_stage = [&](int s, int c) {
        int k0 = c * KC;
        uint32_t base = sb + s * STAGE_B;
        #pragma unroll
        for (int q = 0; q < 8; q++) {
            int o = tid + q * 256;
            int mat = o >> 10, idx = o & 1023, r = idx >> 3, cc = idx & 7;
            uint32_t dst = base + mat * MATB + r * ROWB + cc * 16;
            const __nv_bfloat16* src =
                (mat == 0) ? act + (size_t)(m0 + r) * KPB + k0 + cc * 8
                           : wd + (size_t)(n0 + r) * KPB + k0 + cc * 8;
            cp16(dst, src);
        }
    };

    #pragma unroll
    for (int s = 0; s < NS - 1; s++) { load_stage(s, s); cp_commit(); }

    float acc[4][4][4] = {};

    for (int i = 0; i < NCB; i++) {
        cp_wait<NS-2>();
        __syncthreads();
        uint32_t base = sb + (i % NS) * STAGE_B;
        #pragma unroll
        for (int ks = 0; ks < 4; ks++) {
            int kk = ks * 16;
            uint32_t afr[4][4];
            #pragma unroll
            for (int mf = 0; mf < 4; mf++) {
                uint32_t ad = base + (uint32_t)(wm*64 + mf*16 + (l & 15)) * ROWB
                            + (kk + ((l >> 4) << 3)) * 2;
                LDSM4(afr[mf][0], afr[mf][1], afr[mf][2], afr[mf][3], ad);
            }
            #pragma unroll
            for (int nf = 0; nf < 4; nf++) {
                uint32_t roff = (uint32_t)(wn*32 + nf*8 + (l & 7)) * ROWB
                              + (kk + ((l >> 3) & 1) * 8) * 2;
                uint32_t bfr[2];
                LDSM2(bfr[0], bfr[1], base + MATB + roff);
                #pragma unroll
                for (int mf = 0; mf < 4; mf++)
                    MMA(acc[mf][nf], afr[mf], bfr);
            }
        }
        __syncthreads();
        int nc = i + NS - 1;
        if (nc < NCB) load_stage(nc % NS, nc);
        cp_commit();
    }

    #pragma unroll
    for (int mf = 0; mf < 4; mf++) {
        #pragma unroll
        for (int h2 = 0; h2 < 2; h2++) {
            int gr = m0 + wm*64 + mf*16 + (l >> 2) + h2*8;
            if (gr >= n_rows) continue;
            int colb = n0 + wn*32 + (l & 3)*2;
            if (routed) {
                int t = g_tok[e*T + gr];
                float cwv = g_cw[e*T + gr];
                float* orow = out + (size_t)t * H;
                #pragma unroll
                for (int nf = 0; nf < 4; nf++) {
                    atomicAdd(orow + colb + nf*8,     cwv * acc[mf][nf][2*h2]);
                    atomicAdd(orow + colb + nf*8 + 1, cwv * acc[mf][nf][2*h2+1]);
                }
            } else {
                float sg = g_sg[gr];
                float* orow = out + (size_t)gr * H;
                #pragma unroll
                for (int nf = 0; nf < 4; nf++)
                    *(float2*)(orow + colb + nf*8) =
                        make_float2(sg * acc[mf][nf][2*h2], sg * acc[mf][nf][2*h2+1]);
            }
        }
    }
}

// ---------------------------------------------------------------------------------
extern "C" void kernel_launch(void* const* d_in, const int* in_sizes, int n_in,
                              void* d_out, int out_size)
{
    (void)in_sizes; (void)n_in; (void)out_size;
    const float* x             = (const float*)d_in[0];
    const float* gate_w        = (const float*)d_in[1];
    const float* w_gate        = (const float*)d_in[2];
    const float* w_up          = (const float*)d_in[3];
    const float* w_down        = (const float*)d_in[4];
    const float* sw_gate       = (const float*)d_in[5];
    const float* sw_up         = (const float*)d_in[6];
    const float* sw_down       = (const float*)d_in[7];
    const float* shared_gate_w = (const float*)d_in[8];
    float* out = (float*)d_out;

    cudaFuncSetAttribute(gemm_a_kernel, cudaFuncAttributeMaxDynamicSharedMemorySize, SMEMA);
    cudaFuncSetAttribute(gemm_b_kernel, cudaFuncAttributeMaxDynamicSharedMemorySize, SMEMB);

    // Order chosen so every consumer follows its producer AND launch #6 is a GEMM
    // (for ncu -s 5 -c 1). Deps: gemm_a-shared{1,2,3}; gemm_b-shared{4:g_sg,5,6};
    // scatter{4,8}; routed gemms{9..12}; routed atomicAdds after 7 inits out.
    pack_x_kernel<<<T, 256>>>(x);                                   // 1
    pack_w_kernel<<<dim3(I/32, H/32, 1), 256>>>(sw_gate, H, I, 3);  // 2
    pack_w_kernel<<<dim3(I/32, H/32, 1), 256>>>(sw_up,   H, I, 4);  // 3
    router_kernel<<<T / 8, 256>>>(x, gate_w, shared_gate_w);        // 4 (writes g_sg!)
    pack_w_kernel<<<dim3(H/32, I/32, 1), 256>>>(sw_down, I, H, 5);  // 5
    gemm_a_kernel<<<dim3(I/128, T/128, 1), 256, SMEMA>>>(0);        // 6 <- ncu target
    gemm_b_kernel<<<dim3(H/128, T/128, 1), 256, SMEMB>>>(out, 0);   // 7 stores init out

    zero_cnt_kernel<<<1, 32>>>();                                   // 8
    scatter_kernel<<<T / 256, 256>>>();                             // 9
    pack_w_kernel<<<dim3(I/32, H/32, E), 256>>>(w_gate, H, I, 0);   // 10
    pack_w_kernel<<<dim3(I/32, H/32, E), 256>>>(w_up,   H, I, 1);   // 11
    pack_w_kernel<<<dim3(H/32, I/32, E), 256>>>(w_down, I, H, 2);   // 12

    gemm_a_kernel<<<dim3(I/128, T/128, E), 256, SMEMA>>>(1);        // 13
    gemm_b_kernel<<<dim3(H/128, T/128, E), 256, SMEMB>>>(out, 1);   // 14 atomicAdd
}

// round 14
// speedup vs baseline: 2.5821x; 1.0504x over previous
#include <cuda_runtime.h>
#include <cuda_bf16.h>
#include <cstdint>
#include <math.h>

#define H 1024
#define I 1408
#define E 8
#define T 8192
#define KPA 3072            // 3*H packed K
#define KPB 4224            // 3*I packed K
#define KC  64              // K per chunk
#define NCA 48              // KPA/KC
#define NCB 66              // KPB/KC
#define NS  3               // pipeline stages

// smem: padded rows, 72 bf16 (144B) per 64-element row -> conflict-free ldmatrix
#define ROWB    144
#define MATB    18432       // 128 rows * 144B (A operand)
#define BMATB   9216        // 64 rows * 144B  (B operand, gemm_a)
#define STAGE_A (MATB + 2*BMATB)   // 36864: A + Bg(64) + Bu(64)
#define STAGE_B (2*MATB)           // A + B (gemm_b unchanged)
#define SMEMA   (NS*STAGE_A + 512) // 111104 -> 2 CTAs = 217KB <= 227KB
#define SMEMB   (NS*STAGE_B)

// ---------------- scratch (device globals) ----------------
__device__ __nv_bfloat16 g_xp  [(size_t)T*KPA];      // x packed  [hi|lo|hi]
__device__ __nv_bfloat16 g_wgp [(size_t)E*I*KPA];    // w_gate^T  [hi|hi|lo]
__device__ __nv_bfloat16 g_wup [(size_t)E*I*KPA];
__device__ __nv_bfloat16 g_wdp [(size_t)E*H*KPB];    // w_down^T  [hi|hi|lo]
__device__ __nv_bfloat16 g_swgp[(size_t)I*KPA];
__device__ __nv_bfloat16 g_swup[(size_t)I*KPA];
__device__ __nv_bfloat16 g_swdp[(size_t)H*KPB];
__device__ __nv_bfloat16 g_actp [(size_t)E*T*KPB];   // routed act packed [hi|lo|hi]
__device__ __nv_bfloat16 g_actps[(size_t)T*KPB];     // shared act packed
__device__ int   g_tok[E*T];
__device__ float g_cw [E*T];
__device__ int   g_cnt[E];
__device__ float g_sg [T];
__device__ int   g_ti [T*2];
__device__ float g_tw [T*2];

// ---------------- asm helpers (all baseline sm_80+, safe for sm_100) ----------------
__device__ __forceinline__ uint32_t smem_u32(const void* p) {
    uint32_t a;
    asm("{ .reg .u64 t; cvta.to.shared.u64 t, %1; cvt.u32.u64 %0, t; }" : "=r"(a) : "l"(p));
    return a;
}
__device__ __forceinline__ void cp16(uint32_t s, const void* g) {
    asm volatile("cp.async.cg.shared.global [%0], [%1], 16;" :: "r"(s), "l"(g));
}
__device__ __forceinline__ void cp_commit() { asm volatile("cp.async.commit_group;" ::: "memory"); }
template<int N> __device__ __forceinline__ void cp_wait() {
    asm volatile("cp.async.wait_group %0;" :: "n"(N) : "memory");
}
#define LDSM4(r0,r1,r2,r3,addr) \
    asm volatile("ldmatrix.sync.aligned.m8n8.x4.shared.b16 {%0,%1,%2,%3}, [%4];" \
        : "=r"(r0),"=r"(r1),"=r"(r2),"=r"(r3) : "r"(addr))
#define LDSM2(r0,r1,addr) \
    asm volatile("ldmatrix.sync.aligned.m8n8.x2.shared.b16 {%0,%1}, [%2];" \
        : "=r"(r0),"=r"(r1) : "r"(addr))
#define MMA(d, a, b) \
    asm volatile("mma.sync.aligned.m16n8k16.row.col.f32.bf16.bf16.f32 " \
        "{%0,%1,%2,%3}, {%4,%5,%6,%7}, {%8,%9}, {%0,%1,%2,%3};" \
        : "+f"((d)[0]),"+f"((d)[1]),"+f"((d)[2]),"+f"((d)[3]) \
        : "r"((a)[0]),"r"((a)[1]),"r"((a)[2]),"r"((a)[3]), "r"((b)[0]),"r"((b)[1]))

__device__ __forceinline__ uint32_t pack2(float v0, float v1, uint32_t& lo2) {
    __nv_bfloat16 h0 = __float2bfloat16(v0), h1 = __float2bfloat16(v1);
    __nv_bfloat16 l0 = __float2bfloat16(v0 - __bfloat162float(h0));
    __nv_bfloat16 l1 = __float2bfloat16(v1 - __bfloat162float(h1));
    lo2 = (uint32_t)__bfloat16_as_ushort(l0) | ((uint32_t)__bfloat16_as_ushort(l1) << 16);
    return (uint32_t)__bfloat16_as_ushort(h0) | ((uint32_t)__bfloat16_as_ushort(h1) << 16);
}

// ---------------- router / scatter ----------------
__global__ __launch_bounds__(256) void router_kernel(
    const float* __restrict__ x, const float* __restrict__ gate_w,
    const float* __restrict__ shared_gate_w)
{
    __shared__ float sgw[9][H];
    for (int idx = threadIdx.x; idx < 9 * H; idx += blockDim.x) {
        int e = idx / H, h = idx % H;
        sgw[e][h] = (e < 8) ? gate_w[idx] : shared_gate_w[h];
    }
    __syncthreads();
    int warp = threadIdx.x >> 5, lane = threadIdx.x & 31;
    int t = blockIdx.x * 8 + warp;
    const float4* xr = (const float4*)(x + (size_t)t * H);
    float acc[9];
    #pragma unroll
    for (int e = 0; e < 9; e++) acc[e] = 0.f;
    for (int c = lane; c < H / 4; c += 32) {
        float4 xv = xr[c];
        #pragma unroll
        for (int e = 0; e < 9; e++) {
            float4 gv = ((const float4*)sgw[e])[c];
            acc[e] += xv.x * gv.x + xv.y * gv.y + xv.z * gv.z + xv.w * gv.w;
        }
    }
    #pragma unroll
    for (int e = 0; e < 9; e++)
        #pragma unroll
        for (int o = 16; o > 0; o >>= 1)
            acc[e] += __shfl_xor_sync(0xffffffffu, acc[e], o);
    if (lane == 0) {
        float m = acc[0];
        #pragma unroll
        for (int e = 1; e < 8; e++) m = fmaxf(m, acc[e]);
        float p[8];
        #pragma unroll
        for (int e = 0; e < 8; e++) p[e] = __expf(acc[e] - m);
        int i0 = 0;
        #pragma unroll
        for (int e = 1; e < 8; e++) if (p[e] > p[i0]) i0 = e;
        int i1 = -1;
        #pragma unroll
        for (int e = 0; e < 8; e++) {
            if (e == i0) continue;
            if (i1 < 0 || p[e] > p[i1]) i1 = e;
        }
        float w0 = p[i0], w1 = p[i1], ws = w0 + w1;
        g_ti[t*2+0] = i0; g_tw[t*2+0] = w0/ws;
        g_ti[t*2+1] = i1; g_tw[t*2+1] = w1/ws;
        g_sg[t] = 1.f / (1.f + __expf(-acc[8]));
    }
}

__global__ void zero_cnt_kernel() { if (threadIdx.x < E) g_cnt[threadIdx.x] = 0; }

__global__ void scatter_kernel() {
    int t = blockIdx.x * blockDim.x + threadIdx.x;
    if (t >= T) return;
    #pragma unroll
    for (int k = 0; k < 2; k++) {
        int e = g_ti[t*2+k];
        int pos = atomicAdd(&g_cnt[e], 1);
        g_tok[e*T + pos] = t;
        g_cw [e*T + pos] = g_tw[t*2+k];
    }
}

// ---------------- packing ----------------
__global__ __launch_bounds__(256) void pack_x_kernel(const float* __restrict__ x) {
    int t = blockIdx.x;
    const float2* xr = (const float2*)(x + (size_t)t * H);
    uint32_t* o = (uint32_t*)(g_xp + (size_t)t * KPA);
    #pragma unroll
    for (int q = 0; q < 2; q++) {
        int p = threadIdx.x + q * 256;
        float2 v = xr[p];
        uint32_t ll, hh = pack2(v.x, v.y, ll);
        o[p]        = hh;   // seg0 hi
        o[512 + p]  = ll;   // seg1 lo
        o[1024 + p] = hh;   // seg2 hi
    }
}

// transpose + pack weights: src[R][C] fp32 -> dst[C][3R] bf16 segs (hi|hi|lo)
__global__ __launch_bounds__(256) void pack_w_kernel(const float* __restrict__ src,
                                                     int R, int C, int sel)
{
    __nv_bfloat16* dst =
        sel == 0 ? g_wgp : sel == 1 ? g_wup : sel == 2 ? g_wdp :
        sel == 3 ? g_swgp : sel == 4 ? g_swup : g_swdp;
    size_t so = (size_t)blockIdx.z * R * C;
    size_t dofs = (size_t)blockIdx.z * C * 3 * R;
    __shared__ float tile[32][33];
    int tx = threadIdx.x & 31, tw = threadIdx.x >> 5;
    int r0 = blockIdx.y * 32, c0 = blockIdx.x * 32;
    #pragma unroll
    for (int q = 0; q < 4; q++) {
        int ty = tw + q * 8;
        tile[ty][tx] = src[so + (size_t)(r0 + ty) * C + c0 + tx];
    }
    __syncthreads();
    #pragma unroll
    for (int q = 0; q < 4; q++) {
        int ty = tw + q * 8;
        float v = tile[tx][ty];
        __nv_bfloat16 h = __float2bfloat16(v);
        __nv_bfloat16 l = __float2bfloat16(v - __bfloat162float(h));
        size_t b = dofs + (size_t)(c0 + ty) * 3 * R + (r0 + tx);
        dst[b]       = h;
        dst[b + R]   = h;
        dst[b + 2*R] = l;
    }
}

// -------- phase A: silu(x@Wg)*(x@Wu), 128x64 tile (64 gate + 64 up cols), occ 2 ------
__global__ __launch_bounds__(256, 2) void gemm_a_kernel(int routed) {
    int e = blockIdx.z;
    int n_rows;
    const __nv_bfloat16 *wg, *wu;
    __nv_bfloat16* act;
    const int* tok = nullptr;
    if (routed) {
        n_rows = g_cnt[e];
        wg = g_wgp + (size_t)e * I * KPA;
        wu = g_wup + (size_t)e * I * KPA;
        act = g_actp + (size_t)e * T * KPB;
        tok = g_tok + e * T;
    } else { n_rows = T; wg = g_swgp; wu = g_swup; act = g_actps; }
    int m0 = blockIdx.y * 128;
    if (m0 >= n_rows) return;
    int n0 = blockIdx.x * 64;

    extern __shared__ char smem[];
    uint32_t sb = smem_u32(smem);
    int* srow = (int*)(smem + NS*STAGE_A);
    int tid = threadIdx.x;
    int w = tid >> 5, l = tid & 31, wm = w >> 2, wn = w & 3;   // wm: 2x64 rows, wn: 4x16 cols

    if (tid < 128) {
        int r = m0 + tid;
        srow[tid] = routed ? tok[(r < n_rows) ? r : (n_rows - 1)] : r;
    }
    __syncthreads();

    auto load_stage = [&](int s, int c) {
        int k0 = c * KC;
        uint32_t base = sb + s * STAGE_A;
        #pragma unroll
        for (int q = 0; q < 8; q++) {        // 2048 cp16: A 1024, Bg 512, Bu 512
            int o = tid + q * 256;
            uint32_t dst;
            const __nv_bfloat16* src;
            if (o < 1024) {                  // A: 128 rows x 8 cp16
                int r = o >> 3, cc = o & 7;
                dst = base + r * ROWB + cc * 16;
                src = g_xp + (size_t)srow[r] * KPA + k0 + cc * 8;
            } else if (o < 1536) {           // Bg: 64 rows x 8 cp16
                int o2 = o - 1024;
                int r = o2 >> 3, cc = o2 & 7;
                dst = base + MATB + r * ROWB + cc * 16;
                src = wg + (size_t)(n0 + r) * KPA + k0 + cc * 8;
            } else {                         // Bu
                int o2 = o - 1536;
                int r = o2 >> 3, cc = o2 & 7;
                dst = base + MATB + BMATB + r * ROWB + cc * 16;
                src = wu + (size_t)(n0 + r) * KPA + k0 + cc * 8;
            }
            cp16(dst, src);
        }
    };

    #pragma unroll
    for (int s = 0; s < NS - 1; s++) { load_stage(s, s); cp_commit(); }

    float accg[4][2][4] = {}, accu[4][2][4] = {};

    for (int i = 0; i < NCA; i++) {
        cp_wait<NS-2>();
        __syncthreads();
        uint32_t base = sb + (i % NS) * STAGE_A;
        #pragma unroll
        for (int ks = 0; ks < 4; ks++) {
            int kk = ks * 16;
            uint32_t afr[4][4];
            #pragma unroll
            for (int mf = 0; mf < 4; mf++) {
                uint32_t ad = base + (uint32_t)(wm*64 + mf*16 + (l & 15)) * ROWB
                            + (kk + ((l >> 4) << 3)) * 2;
                LDSM4(afr[mf][0], afr[mf][1], afr[mf][2], afr[mf][3], ad);
            }
            #pragma unroll
            for (int nf = 0; nf < 2; nf++) {
                uint32_t roff = (uint32_t)(wn*16 + nf*8 + (l & 7)) * ROWB
                              + (kk + ((l >> 3) & 1) * 8) * 2;
                uint32_t bg[2], bu[2];
                LDSM2(bg[0], bg[1], base + MATB + roff);
                LDSM2(bu[0], bu[1], base + MATB + BMATB + roff);
                #pragma unroll
                for (int mf = 0; mf < 4; mf++) {
                    MMA(accg[mf][nf], afr[mf], bg);
                    MMA(accu[mf][nf], afr[mf], bu);
                }
            }
        }
        __syncthreads();
        int nc = i + NS - 1;
        if (nc < NCA) load_stage(nc % NS, nc);
        cp_commit();   // always commit (possibly empty) to keep wait invariant
    }

    // epilogue: silu(g)*u, re-split to [hi|lo|hi]
    #pragma unroll
    for (int mf = 0; mf < 4; mf++) {
        #pragma unroll
        for (int h2 = 0; h2 < 2; h2++) {
            int gr = m0 + wm*64 + mf*16 + (l >> 2) + h2*8;
            if (gr >= n_rows) continue;
            __nv_bfloat16* arow = act + (size_t)gr * KPB;
            #pragma unroll
            for (int nf = 0; nf < 2; nf++) {
                float g0 = accg[mf][nf][2*h2], g1 = accg[mf][nf][2*h2+1];
                float u0 = accu[mf][nf][2*h2], u1 = accu[mf][nf][2*h2+1];
                float v0 = g0 * u0 / (1.f + __expf(-g0));
                float v1 = g1 * u1 / (1.f + __expf(-g1));
                uint32_t ll, hh = pack2(v0, v1, ll);
                int col = n0 + wn*16 + nf*8 + (l & 3)*2;
                *(uint32_t*)(arow + col)       = hh;
                *(uint32_t*)(arow + I + col)   = ll;
                *(uint32_t*)(arow + 2*I + col) = hh;
            }
        }
    }
}

// -------- phase B: act @ Wd; routed: out += cw*acc (atomic); shared: out = sg*acc ----
__global__ __launch_bounds__(256, 2) void gemm_b_kernel(float* __restrict__ out, int routed) {
    int e = blockIdx.z;
    int n_rows;
    const __nv_bfloat16 *wd, *act;
    if (routed) {
        n_rows = g_cnt[e];
        wd = g_wdp + (size_t)e * H * KPB;
        act = g_actp + (size_t)e * T * KPB;
    } else { n_rows = T; wd = g_swdp; act = g_actps; }
    int m0 = blockIdx.y * 128;
    if (m0 >= n_rows) return;
    int n0 = blockIdx.x * 128;

    extern __shared__ char smem[];
    uint32_t sb = smem_u32(smem);
    int tid = threadIdx.x;
    int w = tid >> 5, l = tid & 31, wm = w >> 2, wn = w & 3;

    auto load_stage = [&](int s, int c) {
        int k0 = c * KC;
        uint32_t base = sb + s * STAGE_B;
        #pragma unroll
        for (int q = 0; q < 8; q++) {
            int o = tid + q * 256;
            int mat = o >> 10, idx = o & 1023, r = idx >> 3, cc = idx & 7;
            uint32_t dst = base + mat * MATB + r * ROWB + cc * 16;
            const __nv_bfloat16* src =
                (mat == 0) ? act + (size_t)(m0 + r) * KPB + k0 + cc * 8
                           : wd + (size_t)(n0 + r) * KPB + k0 + cc * 8;
            cp16(dst, src);
        }
    };

    #pragma unroll
    for (int s = 0; s < NS - 1; s++) { load_stage(s, s); cp_commit(); }

    float acc[4][4][4] = {};

    for (int i = 0; i < NCB; i++) {
        cp_wait<NS-2>();
        __syncthreads();
        uint32_t base = sb + (i % NS) * STAGE_B;
        #pragma unroll
        for (int ks = 0; ks < 4; ks++) {
            int kk = ks * 16;
            uint32_t afr[4][4];
            #pragma unroll
            for (int mf = 0; mf < 4; mf++) {
                uint32_t ad = base + (uint32_t)(wm*64 + mf*16 + (l & 15)) * ROWB
                            + (kk + ((l >> 4) << 3)) * 2;
                LDSM4(afr[mf][0], afr[mf][1], afr[mf][2], afr[mf][3], ad);
            }
            #pragma unroll
            for (int nf = 0; nf < 4; nf++) {
                uint32_t roff = (uint32_t)(wn*32 + nf*8 + (l & 7)) * ROWB
                              + (kk + ((l >> 3) & 1) * 8) * 2;
                uint32_t bfr[2];
                LDSM2(bfr[0], bfr[1], base + MATB + roff);
                #pragma unroll
                for (int mf = 0; mf < 4; mf++)
                    MMA(acc[mf][nf], afr[mf], bfr);
            }
        }
        __syncthreads();
        int nc = i + NS - 1;
        if (nc < NCB) load_stage(nc % NS, nc);
        cp_commit();
    }

    #pragma unroll
    for (int mf = 0; mf < 4; mf++) {
        #pragma unroll
        for (int h2 = 0; h2 < 2; h2++) {
            int gr = m0 + wm*64 + mf*16 + (l >> 2) + h2*8;
            if (gr >= n_rows) continue;
            int colb = n0 + wn*32 + (l & 3)*2;
            if (routed) {
                int t = g_tok[e*T + gr];
                float cwv = g_cw[e*T + gr];
                float* orow = out + (size_t)t * H;
                #pragma unroll
                for (int nf = 0; nf < 4; nf++) {
                    atomicAdd(orow + colb + nf*8,     cwv * acc[mf][nf][2*h2]);
                    atomicAdd(orow + colb + nf*8 + 1, cwv * acc[mf][nf][2*h2+1]);
                }
            } else {
                float sg = g_sg[gr];
                float* orow = out + (size_t)gr * H;
                #pragma unroll
                for (int nf = 0; nf < 4; nf++)
                    *(float2*)(orow + colb + nf*8) =
                        make_float2(sg * acc[mf][nf][2*h2], sg * acc[mf][nf][2*h2+1]);
            }
        }
    }
}

// ---------------------------------------------------------------------------------
extern "C" void kernel_launch(void* const* d_in, const int* in_sizes, int n_in,
                              void* d_out, int out_size)
{
    (void)in_sizes; (void)n_in; (void)out_size;
    const float* x             = (const float*)d_in[0];
    const float* gate_w        = (const float*)d_in[1];
    const float* w_gate        = (const float*)d_in[2];
    const float* w_up          = (const float*)d_in[3];
    const float* w_down        = (const float*)d_in[4];
    const float* sw_gate       = (const float*)d_in[5];
    const float* sw_up         = (const float*)d_in[6];
    const float* sw_down       = (const float*)d_in[7];
    const float* shared_gate_w = (const float*)d_in[8];
    float* out = (float*)d_out;

    cudaFuncSetAttribute(gemm_a_kernel, cudaFuncAttributeMaxDynamicSharedMemorySize, SMEMA);
    cudaFuncSetAttribute(gemm_b_kernel, cudaFuncAttributeMaxDynamicSharedMemorySize, SMEMB);

    // Order: every consumer follows its producer; launch #6 is a GEMM for ncu.
    pack_x_kernel<<<T, 256>>>(x);                                   // 1
    pack_w_kernel<<<dim3(I/32, H/32, 1), 256>>>(sw_gate, H, I, 3);  // 2
    pack_w_kernel<<<dim3(I/32, H/32, 1), 256>>>(sw_up,   H, I, 4);  // 3
    router_kernel<<<T / 8, 256>>>(x, gate_w, shared_gate_w);        // 4 (writes g_sg)
    pack_w_kernel<<<dim3(H/32, I/32, 1), 256>>>(sw_down, I, H, 5);  // 5
    gemm_a_kernel<<<dim3(I/64, T/128, 1), 256, SMEMA>>>(0);         // 6
    gemm_b_kernel<<<dim3(H/128, T/128, 1), 256, SMEMB>>>(out, 0);   // 7 stores init out

    zero_cnt_kernel<<<1, 32>>>();                                   // 8
    scatter_kernel<<<T / 256, 256>>>();                             // 9
    pack_w_kernel<<<dim3(I/32, H/32, E), 256>>>(w_gate, H, I, 0);   // 10
    pack_w_kernel<<<dim3(I/32, H/32, E), 256>>>(w_up,   H, I, 1);   // 11
    pack_w_kernel<<<dim3(H/32, I/32, E), 256>>>(w_down, I, H, 2);   // 12

    gemm_a_kernel<<<dim3(I/64, T/128, E), 256, SMEMA>>>(1);         // 13
    gemm_b_kernel<<<dim3(H/128, T/128, E), 256, SMEMB>>>(out, 1);   // 14 atomicAdd
}

// round 16
// speedup vs baseline: 2.6278x; 1.0177x over previous
#include <cuda_runtime.h>
#include <cuda_bf16.h>
#include <cstdint>
#include <math.h>

#define H 1024
#define I 1408
#define E 8
#define T 8192
#define KPA 3072            // 3*H packed K
#define KPB 4224            // 3*I packed K
#define KC  64              // K per chunk
#define NCA 48              // KPA/KC
#define NCB 66              // KPB/KC
#define NS  3               // pipeline stages

// smem: padded rows, 72 bf16 (144B) per 64-element row -> conflict-free ldmatrix
#define ROWB    144
#define MATB    18432       // 128 rows * 144B (A operand)
#define BMATB   9216        // 64 rows * 144B  (B operand, gemm_a)
#define STAGE_A (MATB + 2*BMATB)   // 36864: A + Bg(64) + Bu(64)
#define STAGE_B (2*MATB)           // A + B
#define SMEMA   (NS*STAGE_A + 512) // 111104 -> 2 CTAs = 217KB <= 227KB
#define SMEMB   (NS*STAGE_B)

// ---------------- scratch (device globals) ----------------
__device__ __nv_bfloat16 g_xp  [(size_t)T*KPA];      // x packed  [hi|lo|hi]
__device__ __nv_bfloat16 g_wgp [(size_t)E*I*KPA];    // w_gate^T  [hi|hi|lo]
__device__ __nv_bfloat16 g_wup [(size_t)E*I*KPA];
__device__ __nv_bfloat16 g_wdp [(size_t)E*H*KPB];    // w_down^T  [hi|hi|lo]
__device__ __nv_bfloat16 g_swgp[(size_t)I*KPA];
__device__ __nv_bfloat16 g_swup[(size_t)I*KPA];
__device__ __nv_bfloat16 g_swdp[(size_t)H*KPB];
__device__ __nv_bfloat16 g_actp [(size_t)E*T*KPB];   // routed act packed [hi|lo|hi]
__device__ __nv_bfloat16 g_actps[(size_t)T*KPB];     // shared act packed
__device__ int   g_tok[E*T];
__device__ float g_cw [E*T];
__device__ int   g_cnt[E];
__device__ float g_sg [T];
__device__ int   g_ti [T*2];
__device__ float g_tw [T*2];

// ---------------- asm helpers (all baseline sm_80+, safe for sm_100) ----------------
__device__ __forceinline__ uint32_t smem_u32(const void* p) {
    uint32_t a;
    asm("{ .reg .u64 t; cvta.to.shared.u64 t, %1; cvt.u32.u64 %0, t; }" : "=r"(a) : "l"(p));
    return a;
}
__device__ __forceinline__ void cp16(uint32_t s, const void* g) {
    asm volatile("cp.async.cg.shared.global [%0], [%1], 16;" :: "r"(s), "l"(g));
}
__device__ __forceinline__ void cp_commit() { asm volatile("cp.async.commit_group;" ::: "memory"); }
template<int N> __device__ __forceinline__ void cp_wait() {
    asm volatile("cp.async.wait_group %0;" :: "n"(N) : "memory");
}
#define LDSM4(r0,r1,r2,r3,addr) \
    asm volatile("ldmatrix.sync.aligned.m8n8.x4.shared.b16 {%0,%1,%2,%3}, [%4];" \
        : "=r"(r0),"=r"(r1),"=r"(r2),"=r"(r3) : "r"(addr))
#define MMA(d, a, b) \
    asm volatile("mma.sync.aligned.m16n8k16.row.col.f32.bf16.bf16.f32 " \
        "{%0,%1,%2,%3}, {%4,%5,%6,%7}, {%8,%9}, {%0,%1,%2,%3};" \
        : "+f"((d)[0]),"+f"((d)[1]),"+f"((d)[2]),"+f"((d)[3]) \
        : "r"((a)[0]),"r"((a)[1]),"r"((a)[2]),"r"((a)[3]), "r"((b)[0]),"r"((b)[1]))

__device__ __forceinline__ uint32_t pack2(float v0, float v1, uint32_t& lo2) {
    __nv_bfloat16 h0 = __float2bfloat16(v0), h1 = __float2bfloat16(v1);
    __nv_bfloat16 l0 = __float2bfloat16(v0 - __bfloat162float(h0));
    __nv_bfloat16 l1 = __float2bfloat16(v1 - __bfloat162float(h1));
    lo2 = (uint32_t)__bfloat16_as_ushort(l0) | ((uint32_t)__bfloat16_as_ushort(l1) << 16);
    return (uint32_t)__bfloat16_as_ushort(h0) | ((uint32_t)__bfloat16_as_ushort(h1) << 16);
}

// ---------------- router / scatter ----------------
__global__ __launch_bounds__(256) void router_kernel(
    const float* __restrict__ x, const float* __restrict__ gate_w,
    const float* __restrict__ shared_gate_w)
{
    __shared__ float sgw[9][H];
    for (int idx = threadIdx.x; idx < 9 * H; idx += blockDim.x) {
        int e = idx / H, h = idx % H;
        sgw[e][h] = (e < 8) ? gate_w[idx] : shared_gate_w[h];
    }
    __syncthreads();
    int warp = threadIdx.x >> 5, lane = threadIdx.x & 31;
    int t = blockIdx.x * 8 + warp;
    const float4* xr = (const float4*)(x + (size_t)t * H);
    float acc[9];
    #pragma unroll
    for (int e = 0; e < 9; e++) acc[e] = 0.f;
    for (int c = lane; c < H / 4; c += 32) {
        float4 xv = xr[c];
        #pragma unroll
        for (int e = 0; e < 9; e++) {
            float4 gv = ((const float4*)sgw[e])[c];
            acc[e] += xv.x * gv.x + xv.y * gv.y + xv.z * gv.z + xv.w * gv.w;
        }
    }
    #pragma unroll
    for (int e = 0; e < 9; e++)
        #pragma unroll
        for (int o = 16; o > 0; o >>= 1)
            acc[e] += __shfl_xor_sync(0xffffffffu, acc[e], o);
    if (lane == 0) {
        float m = acc[0];
        #pragma unroll
        for (int e = 1; e < 8; e++) m = fmaxf(m, acc[e]);
        float p[8];
        #pragma unroll
        for (int e = 0; e < 8; e++) p[e] = __expf(acc[e] - m);
        int i0 = 0;
        #pragma unroll
        for (int e = 1; e < 8; e++) if (p[e] > p[i0]) i0 = e;
        int i1 = -1;
        #pragma unroll
        for (int e = 0; e < 8; e++) {
            if (e == i0) continue;
            if (i1 < 0 || p[e] > p[i1]) i1 = e;
        }
        float w0 = p[i0], w1 = p[i1], ws = w0 + w1;
        g_ti[t*2+0] = i0; g_tw[t*2+0] = w0/ws;
        g_ti[t*2+1] = i1; g_tw[t*2+1] = w1/ws;
        g_sg[t] = 1.f / (1.f + __expf(-acc[8]));
    }
}

__global__ void zero_cnt_kernel() { if (threadIdx.x < E) g_cnt[threadIdx.x] = 0; }

__global__ void scatter_kernel() {
    int t = blockIdx.x * blockDim.x + threadIdx.x;
    if (t >= T) return;
    #pragma unroll
    for (int k = 0; k < 2; k++) {
        int e = g_ti[t*2+k];
        int pos = atomicAdd(&g_cnt[e], 1);
        g_tok[e*T + pos] = t;
        g_cw [e*T + pos] = g_tw[t*2+k];
    }
}

// ---------------- packing ----------------
__global__ __launch_bounds__(256) void pack_x_kernel(const float* __restrict__ x) {
    int t = blockIdx.x;
    const float2* xr = (const float2*)(x + (size_t)t * H);
    uint32_t* o = (uint32_t*)(g_xp + (size_t)t * KPA);
    #pragma unroll
    for (int q = 0; q < 2; q++) {
        int p = threadIdx.x + q * 256;
        float2 v = xr[p];
        uint32_t ll, hh = pack2(v.x, v.y, ll);
        o[p]        = hh;   // seg0 hi
        o[512 + p]  = ll;   // seg1 lo
        o[1024 + p] = hh;   // seg2 hi
    }
}

// transpose + pack weights: src[R][C] fp32 -> dst[C][3R] bf16 segs (hi|hi|lo)
__global__ __launch_bounds__(256) void pack_w_kernel(const float* __restrict__ src,
                                                     int R, int C, int sel)
{
    __nv_bfloat16* dst =
        sel == 0 ? g_wgp : sel == 1 ? g_wup : sel == 2 ? g_wdp :
        sel == 3 ? g_swgp : sel == 4 ? g_swup : g_swdp;
    size_t so = (size_t)blockIdx.z * R * C;
    size_t dofs = (size_t)blockIdx.z * C * 3 * R;
    __shared__ float tile[32][33];
    int tx = threadIdx.x & 31, tw = threadIdx.x >> 5;
    int r0 = blockIdx.y * 32, c0 = blockIdx.x * 32;
    #pragma unroll
    for (int q = 0; q < 4; q++) {
        int ty = tw + q * 8;
        tile[ty][tx] = src[so + (size_t)(r0 + ty) * C + c0 + tx];
    }
    __syncthreads();
    #pragma unroll
    for (int q = 0; q < 4; q++) {
        int ty = tw + q * 8;
        float v = tile[tx][ty];
        __nv_bfloat16 h = __float2bfloat16(v);
        __nv_bfloat16 l = __float2bfloat16(v - __bfloat162float(h));
        size_t b = dofs + (size_t)(c0 + ty) * 3 * R + (r0 + tx);
        dst[b]       = h;
        dst[b + R]   = h;
        dst[b + 2*R] = l;
    }
}

// -------- phase A: silu(x@Wg)*(x@Wu), 128x64 tile, occ 2, single-sync pipeline ------
__global__ __launch_bounds__(256, 2) void gemm_a_kernel(int routed) {
    int e = blockIdx.z;
    int n_rows;
    const __nv_bfloat16 *wg, *wu;
    __nv_bfloat16* act;
    const int* tok = nullptr;
    if (routed) {
        n_rows = g_cnt[e];
        wg = g_wgp + (size_t)e * I * KPA;
        wu = g_wup + (size_t)e * I * KPA;
        act = g_actp + (size_t)e * T * KPB;
        tok = g_tok + e * T;
    } else { n_rows = T; wg = g_swgp; wu = g_swup; act = g_actps; }
    int m0 = blockIdx.y * 128;
    if (m0 >= n_rows) return;
    int n0 = blockIdx.x * 64;

    extern __shared__ char smem[];
    uint32_t sb = smem_u32(smem);
    int* srow = (int*)(smem + NS*STAGE_A);
    int tid = threadIdx.x;
    int w = tid >> 5, l = tid & 31, wm = w >> 2, wn = w & 3;

    if (tid < 128) {
        int r = m0 + tid;
        srow[tid] = routed ? tok[(r < n_rows) ? r : (n_rows - 1)] : r;
    }
    __syncthreads();

    auto load_stage = [&](int s, int c) {
        int k0 = c * KC;
        uint32_t base = sb + s * STAGE_A;
        #pragma unroll
        for (int q = 0; q < 8; q++) {        // 2048 cp16: A 1024, Bg 512, Bu 512
            int o = tid + q * 256;
            uint32_t dst;
            const __nv_bfloat16* src;
            if (o < 1024) {                  // A: 128 rows x 8 cp16
                int r = o >> 3, cc = o & 7;
                dst = base + r * ROWB + cc * 16;
                src = g_xp + (size_t)srow[r] * KPA + k0 + cc * 8;
            } else if (o < 1536) {           // Bg: 64 rows x 8 cp16
                int o2 = o - 1024;
                int r = o2 >> 3, cc = o2 & 7;
                dst = base + MATB + r * ROWB + cc * 16;
                src = wg + (size_t)(n0 + r) * KPA + k0 + cc * 8;
            } else {                         // Bu
                int o2 = o - 1536;
                int r = o2 >> 3, cc = o2 & 7;
                dst = base + MATB + BMATB + r * ROWB + cc * 16;
                src = wu + (size_t)(n0 + r) * KPA + k0 + cc * 8;
            }
            cp16(dst, src);
        }
    };

    #pragma unroll
    for (int s = 0; s < NS - 1; s++) { load_stage(s, s); cp_commit(); }

    float accg[4][2][4] = {}, accu[4][2][4] = {};

    for (int i = 0; i < NCA; i++) {
        cp_wait<NS-2>();
        __syncthreads();                       // chunk i ready; all warps past iter i-1
        int nc = i + NS - 1;
        if (nc < NCA) load_stage(nc % NS, nc); // refills slot of chunk i-1: safe
        cp_commit();                           // always commit to keep wait invariant
        uint32_t base = sb + (i % NS) * STAGE_A;
        #pragma unroll
        for (int ks = 0; ks < 4; ks++) {
            int kk = ks * 16;
            uint32_t afr[4][4];
            #pragma unroll
            for (int mf = 0; mf < 4; mf++) {
                uint32_t ad = base + (uint32_t)(wm*64 + mf*16 + (l & 15)) * ROWB
                            + (kk + ((l >> 4) << 3)) * 2;
                LDSM4(afr[mf][0], afr[mf][1], afr[mf][2], afr[mf][3], ad);
            }
            // B via x4: lanes 0-15 -> rows r..r+7 (cols kk / kk+8), 16-31 -> rows +8
            uint32_t bg[4], bu[4];
            uint32_t roff = (uint32_t)(wn*16 + ((l >> 4) << 3) + (l & 7)) * ROWB
                          + (kk + ((l >> 3) & 1) * 8) * 2;
            LDSM4(bg[0], bg[1], bg[2], bg[3], base + MATB + roff);
            LDSM4(bu[0], bu[1], bu[2], bu[3], base + MATB + BMATB + roff);
            #pragma unroll
            for (int mf = 0; mf < 4; mf++) {
                MMA(accg[mf][0], afr[mf], bg);
                MMA(accg[mf][1], afr[mf], bg + 2);
                MMA(accu[mf][0], afr[mf], bu);
                MMA(accu[mf][1], afr[mf], bu + 2);
            }
        }
    }

    // epilogue: silu(g)*u, re-split to [hi|lo|hi]
    #pragma unroll
    for (int mf = 0; mf < 4; mf++) {
        #pragma unroll
        for (int h2 = 0; h2 < 2; h2++) {
            int gr = m0 + wm*64 + mf*16 + (l >> 2) + h2*8;
            if (gr >= n_rows) continue;
            __nv_bfloat16* arow = act + (size_t)gr * KPB;
            #pragma unroll
            for (int nf = 0; nf < 2; nf++) {
                float g0 = accg[mf][nf][2*h2], g1 = accg[mf][nf][2*h2+1];
                float u0 = accu[mf][nf][2*h2], u1 = accu[mf][nf][2*h2+1];
                float v0 = g0 * u0 / (1.f + __expf(-g0));
                float v1 = g1 * u1 / (1.f + __expf(-g1));
                uint32_t ll, hh = pack2(v0, v1, ll);
                int col = n0 + wn*16 + nf*8 + (l & 3)*2;
                *(uint32_t*)(arow + col)       = hh;
                *(uint32_t*)(arow + I + col)   = ll;
                *(uint32_t*)(arow + 2*I + col) = hh;
            }
        }
    }
}

// -------- phase B: act @ Wd; routed: out += cw*acc (atomic); shared: out = sg*acc ----
__global__ __launch_bounds__(256, 2) void gemm_b_kernel(float* __restrict__ out, int routed) {
    int e = blockIdx.z;
    int n_rows;
    const __nv_bfloat16 *wd, *act;
    if (routed) {
        n_rows = g_cnt[e];
        wd = g_wdp + (size_t)e * H * KPB;
        act = g_actp + (size_t)e * T * KPB;
    } else { n_rows = T; wd = g_swdp; act = g_actps; }
    int m0 = blockIdx.y * 128;
    if (m0 >= n_rows) return;
    int n0 = blockIdx.x * 128;

    extern __shared__ char smem[];
    uint32_t sb = smem_u32(smem);
    int tid = threadIdx.x;
    int w = tid >> 5, l = tid & 31, wm = w >> 2, wn = w & 3;

    auto load_stage = [&](int s, int c) {
        int k0 = c * KC;
        uint32_t base = sb + s * STAGE_B;
        #pragma unroll
        for (int q = 0; q < 8; q++) {
            int o = tid + q * 256;
            int mat = o >> 10, idx = o & 1023, r = idx >> 3, cc = idx & 7;
            uint32_t dst = base + mat * MATB + r * ROWB + cc * 16;
            const __nv_bfloat16* src =
                (mat == 0) ? act + (size_t)(m0 + r) * KPB + k0 + cc * 8
                           : wd + (size_t)(n0 + r) * KPB + k0 + cc * 8;
            cp16(dst, src);
        }
    };

    #pragma unroll
    for (int s = 0; s < NS - 1; s++) { load_stage(s, s); cp_commit(); }

    float acc[4][4][4] = {};

    for (int i = 0; i < NCB; i++) {
        cp_wait<NS-2>();
        __syncthreads();
        int nc = i + NS - 1;
        if (nc < NCB) load_stage(nc % NS, nc);
        cp_commit();
        uint32_t base = sb + (i % NS) * STAGE_B;
        #pragma unroll
        for (int ks = 0; ks < 4; ks++) {
            int kk = ks * 16;
            uint32_t afr[4][4];
            #pragma unroll
            for (int mf = 0; mf < 4; mf++) {
                uint32_t ad = base + (uint32_t)(wm*64 + mf*16 + (l & 15)) * ROWB
                            + (kk + ((l >> 4) << 3)) * 2;
                LDSM4(afr[mf][0], afr[mf][1], afr[mf][2], afr[mf][3], ad);
            }
            #pragma unroll
            for (int nf2 = 0; nf2 < 2; nf2++) {
                uint32_t bfr[4];
                uint32_t roff = (uint32_t)(wn*32 + nf2*16 + ((l >> 4) << 3) + (l & 7)) * ROWB
                              + (kk + ((l >> 3) & 1) * 8) * 2;
                LDSM4(bfr[0], bfr[1], bfr[2], bfr[3], base + MATB + roff);
                #pragma unroll
                for (int mf = 0; mf < 4; mf++) {
                    MMA(acc[mf][nf2*2],   afr[mf], bfr);
                    MMA(acc[mf][nf2*2+1], afr[mf], bfr + 2);
                }
            }
        }
    }

    #pragma unroll
    for (int mf = 0; mf < 4; mf++) {
        #pragma unroll
        for (int h2 = 0; h2 < 2; h2++) {
            int gr = m0 + wm*64 + mf*16 + (l >> 2) + h2*8;
            if (gr >= n_rows) continue;
            int colb = n0 + wn*32 + (l & 3)*2;
            if (routed) {
                int t = g_tok[e*T + gr];
                float cwv = g_cw[e*T + gr];
                float* orow = out + (size_t)t * H;
                #pragma unroll
                for (int nf = 0; nf < 4; nf++) {
                    atomicAdd(orow + colb + nf*8,     cwv * acc[mf][nf][2*h2]);
                    atomicAdd(orow + colb + nf*8 + 1, cwv * acc[mf][nf][2*h2+1]);
                }
            } else {
                float sg = g_sg[gr];
                float* orow = out + (size_t)gr * H;
                #pragma unroll
                for (int nf = 0; nf < 4; nf++)
                    *(float2*)(orow + colb + nf*8) =
                        make_float2(sg * acc[mf][nf][2*h2], sg * acc[mf][nf][2*h2+1]);
            }
        }
    }
}

// ---------------------------------------------------------------------------------
extern "C" void kernel_launch(void* const* d_in, const int* in_sizes, int n_in,
                              void* d_out, int out_size)
{
    (void)in_sizes; (void)n_in; (void)out_size;
    const float* x             = (const float*)d_in[0];
    const float* gate_w        = (const float*)d_in[1];
    const float* w_gate        = (const float*)d_in[2];
    const float* w_up          = (const float*)d_in[3];
    const float* w_down        = (const float*)d_in[4];
    const float* sw_gate       = (const float*)d_in[5];
    const float* sw_up         = (const float*)d_in[6];
    const float* sw_down       = (const float*)d_in[7];
    const float* shared_gate_w = (const float*)d_in[8];
    float* out = (float*)d_out;

    cudaFuncSetAttribute(gemm_a_kernel, cudaFuncAttributeMaxDynamicSharedMemorySize, SMEMA);
    cudaFuncSetAttribute(gemm_b_kernel, cudaFuncAttributeMaxDynamicSharedMemorySize, SMEMB);

    // Order: every consumer follows its producer; launch #6 is a GEMM for ncu.
    pack_x_kernel<<<T, 256>>>(x);                                   // 1
    pack_w_kernel<<<dim3(I/32, H/32, 1), 256>>>(sw_gate, H, I, 3);  // 2
    pack_w_kernel<<<dim3(I/32, H/32, 1), 256>>>(sw_up,   H, I, 4);  // 3
    router_kernel<<<T / 8, 256>>>(x, gate_w, shared_gate_w);        // 4 (writes g_sg)
    pack_w_kernel<<<dim3(H/32, I/32, 1), 256>>>(sw_down, I, H, 5);  // 5
    gemm_a_kernel<<<dim3(I/64, T/128, 1), 256, SMEMA>>>(0);         // 6
    gemm_b_kernel<<<dim3(H/128, T/128, 1), 256, SMEMB>>>(out, 0);   // 7 stores init out

    zero_cnt_kernel<<<1, 32>>>();                                   // 8
    scatter_kernel<<<T / 256, 256>>>();                             // 9
    pack_w_kernel<<<dim3(I/32, H/32, E), 256>>>(w_gate, H, I, 0);   // 10
    pack_w_kernel<<<dim3(I/32, H/32, E), 256>>>(w_up,   H, I, 1);   // 11
    pack_w_kernel<<<dim3(H/32, I/32, E), 256>>>(w_down, I, H, 2);   // 12

    gemm_a_kernel<<<dim3(I/64, T/128, E), 256, SMEMA>>>(1);         // 13
    gemm_b_kernel<<<dim3(H/128, T/128, E), 256, SMEMB>>>(out, 1);   // 14 atomicAdd
}